// round 9
// baseline (speedup 1.0000x reference)
#include <cstdint>
#include <stdint.h>
#include <cuda_runtime.h>
#include <cuda_fp16.h>

#define B_TOT   8192
#define NTOK    49
#define CDIM    192
#define NH      6
#define HDIM    32
#define SCALE_F 0.17677669529663687f   // 1/sqrt(32)
#define QKV_ROWS (B_TOT * NTOK)        // 401408

// fp16 copies of the weights (converted by conv_w each call; deterministic)
__device__ __align__(16) __half g_wqkv[CDIM * 3 * CDIM];   // [192][576] row-major
__device__ __align__(16) __half g_wproj[CDIM * CDIM];      // [192][192] row-major
// fp16 qkv scratch: [B_*N][576] row-major
__device__ __align__(16) __half g_qkv[QKV_ROWS * 3 * CDIM];

__global__ void conv_w(const float* __restrict__ wq, const float* __restrict__ wp) {
    int i = blockIdx.x * 256 + threadIdx.x;
    if (i < CDIM * 3 * CDIM) g_wqkv[i]  = __float2half_rn(wq[i]);
    if (i < CDIM * CDIM)     g_wproj[i] = __float2half_rn(wp[i]);
}

// ---------------------------------------------------------------------------
// raw-PTX helpers
// ---------------------------------------------------------------------------
__device__ __forceinline__ unsigned smaddr(const void* p) {
    return (unsigned)__cvta_generic_to_shared(p);
}
__device__ __forceinline__ void ldsm4(unsigned& r0, unsigned& r1, unsigned& r2, unsigned& r3,
                                      unsigned a) {
    asm volatile("ldmatrix.sync.aligned.m8n8.x4.shared.b16 {%0,%1,%2,%3}, [%4];"
                 : "=r"(r0), "=r"(r1), "=r"(r2), "=r"(r3) : "r"(a));
}
__device__ __forceinline__ void ldsm4t(unsigned& r0, unsigned& r1, unsigned& r2, unsigned& r3,
                                       unsigned a) {
    asm volatile("ldmatrix.sync.aligned.m8n8.x4.trans.shared.b16 {%0,%1,%2,%3}, [%4];"
                 : "=r"(r0), "=r"(r1), "=r"(r2), "=r"(r3) : "r"(a));
}
__device__ __forceinline__ void mma16816(float* c,
                                         unsigned a0, unsigned a1, unsigned a2, unsigned a3,
                                         unsigned b0, unsigned b1) {
    asm volatile(
        "mma.sync.aligned.m16n8k16.row.col.f32.f16.f16.f32 "
        "{%0,%1,%2,%3},{%4,%5,%6,%7},{%8,%9},{%0,%1,%2,%3};"
        : "+f"(c[0]), "+f"(c[1]), "+f"(c[2]), "+f"(c[3])
        : "r"(a0), "r"(a1), "r"(a2), "r"(a3), "r"(b0), "r"(b1));
}
__device__ __forceinline__ unsigned pack_h2(float a, float b) {
    __half2 h = __floats2half2_rn(a, b);
    return *(unsigned*)&h;
}

// ============================================================================
// Kernel 1: QKV projection GEMM, raw mma.
// Warp owns 16 rows; A (16x192) in registers across all chunks; each 96-col
// weight chunk computed in TWO 48-col halves so the accumulator is only 24
// regs -> fits 85-reg budget for 3 CTAs/SM.
// smem: wsc half[192][104] = 39936 B
// ============================================================================
#define K1_SMEM 39936

__global__ void __launch_bounds__(256, 3)
qkv_gemm(const float* __restrict__ x, const float* __restrict__ bqkv)
{
    extern __shared__ __align__(128) char smem[];
    __half* wsc = (__half*)smem;                    // ld 104

    const int tid  = threadIdx.x;
    const int w    = tid >> 5;
    const int lane = tid & 31;
    const int rbase = blockIdx.x * 128 + w * 16;
    const int c0 = 2 * (lane & 3);

    // ---- A-fragments straight from gmem (fp32 -> fp16), held across chunks ----
    unsigned A[12][4];
    {
        const int r0 = rbase + (lane >> 2);
        const float* xr0 = x + (size_t)r0 * CDIM;
        const float* xr8 = xr0 + 8 * CDIM;
        #pragma unroll
        for (int kt = 0; kt < 12; kt++) {
            int c = kt * 16 + c0;
            float2 v;
            v = *(const float2*)(xr0 + c);     A[kt][0] = pack_h2(v.x, v.y);
            v = *(const float2*)(xr8 + c);     A[kt][1] = pack_h2(v.x, v.y);
            v = *(const float2*)(xr0 + c + 8); A[kt][2] = pack_h2(v.x, v.y);
            v = *(const float2*)(xr8 + c + 8); A[kt][3] = pack_h2(v.x, v.y);
        }
    }

    const int orow = rbase + (lane >> 2);

    for (int nc = 0; nc < 6; nc++) {
        __syncthreads();   // prior chunk's ldsm reads of wsc complete
        for (int i = tid; i < 2304; i += 256) {      // 192 rows * 12 int4
            int row = i / 12, v8 = i % 12;
            const int4* s = (const int4*)(g_wqkv + row * 576 + nc * 96 + v8 * 8);
            *(int4*)(wsc + row * 104 + v8 * 8) = *s;
        }
        __syncthreads();

        #pragma unroll
        for (int half = 0; half < 2; half++) {       // 48-col halves
            float C[6][4];
            #pragma unroll
            for (int n = 0; n < 6; n++)
                #pragma unroll
                for (int e = 0; e < 4; e++) C[n][e] = 0.0f;

            #pragma unroll
            for (int kt = 0; kt < 12; kt++) {
                int rB = kt * 16 + (lane & 7) + ((lane >> 3) & 1) * 8;
                #pragma unroll
                for (int np = 0; np < 3; np++) {
                    unsigned b0, b1, b2, b3;
                    int cB = half * 48 + np * 16 + (lane >> 4) * 8;
                    ldsm4t(b0, b1, b2, b3, smaddr(wsc + rB * 104 + cB));
                    mma16816(C[2 * np],     A[kt][0], A[kt][1], A[kt][2], A[kt][3], b0, b1);
                    mma16816(C[2 * np + 1], A[kt][0], A[kt][1], A[kt][2], A[kt][3], b2, b3);
                }
            }

            // ---- epilogue: +bias, fp16, direct global store ----
            __half* g0 = g_qkv + (size_t)orow * 576 + nc * 96 + half * 48;
            __half* g8 = g0 + (size_t)8 * 576;
            #pragma unroll
            for (int n = 0; n < 6; n++) {
                int col = 8 * n + c0;
                float2 bb = *(const float2*)(bqkv + nc * 96 + half * 48 + col);
                *(__half2*)(g0 + col) = __floats2half2_rn(C[n][0] + bb.x, C[n][1] + bb.y);
                *(__half2*)(g8 + col) = __floats2half2_rn(C[n][2] + bb.x, C[n][3] + bb.y);
            }
        }
    }
}

// ============================================================================
// Kernel 2: fused attention + output projection, one CTA per batch item.
// Attention: register-resident, 2 heads/phase (as round 7/8).
// Projection: Wproj staged in 96-row K-chunks (19.9KB, unioned over qbuf2)
// so smem = 52.2KB -> 4 CTAs/SM under a 64-reg cap.
// ============================================================================
// smem: Oall  half [64][200]   @0      25600
//       qbuf2 half 2x[64][104] @25600  26624  (attention)
//       wp    half [96][104]   @25600  19968  (projection; union w/ qbuf2)
//       mbs   u32 [2]          @52224      8  -> total 52232 (pad 52240)
#define K2_SMEM 52240

__global__ void __launch_bounds__(256, 4)
attn_proj(const int* __restrict__ mask, const float* __restrict__ bproj,
          float* __restrict__ out)
{
    extern __shared__ __align__(128) char smem[];
    __half*   Oall  = (__half*)(smem);               // ld 200
    __half*   qbuf2 = (__half*)(smem + 25600);       // 2 heads, each ld 104 (Q|K|V)
    __half*   wp    = (__half*)(smem + 25600);       // ld 104 (union w/ qbuf2)
    unsigned* mbs   = (unsigned*)(smem + 52224);

    const int b    = blockIdx.x;
    const int tid  = threadIdx.x;
    const int w    = tid >> 5;
    const int lane = tid & 31;
    const int q2   = 2 * (lane & 3);                 // col offset within 8-col tile

    // ---- mask -> 64-bit ballot in smem ----
    {
        int valid = 0;
        if (tid < 64) valid = (tid < NTOK) ? (mask[b * NTOK + tid] != 0) : 0;
        unsigned bal = __ballot_sync(0xffffffffu, valid);
        if (w < 2 && lane == 0) mbs[w] = bal;
    }
    __syncthreads();
    const unsigned mb0 = mbs[0], mb1 = mbs[1];

    const __half* qkv_b = g_qkv + (size_t)b * NTOK * 576;

    const int hh = w >> 2;                 // which head of the pair this warp works on
    const int m  = w & 3;                  // m-tile (16 q rows)
    __half* qh = qbuf2 + hh * 6656;        // 6656 halves = 13312 B per head buffer

    for (int hp = 0; hp < 3; hp++) {
        __syncthreads();   // prior pair's ldmatrix reads of qbuf2 complete

        // ---- stage 2 heads: qbuf[hx][64][96] = Q|K|V cols of head hp*2+hx ----
        for (int i = tid; i < 2 * NTOK * 12; i += 256) {
            int hx = i / (NTOK * 12);
            int j  = i - hx * (NTOK * 12);
            int row = j / 12, j12 = j % 12;
            int seg = j12 >> 2, hv = j12 & 3;
            int h = hp * 2 + hx;
            const int4* s = (const int4*)(qkv_b + row * 576 + seg * 192 + h * HDIM + hv * 8);
            *(int4*)(qbuf2 + hx * 6656 + row * 104 + seg * 32 + hv * 8) = *s;
        }
        for (int i = tid; i < 2 * 15 * 13; i += 256) {   // zero-pad rows 49..63
            int hx = i / 195, j = i - hx * 195;
            int r = 49 + j / 13, v8 = j % 13;
            *(int4*)(qbuf2 + hx * 6656 + r * 104 + v8 * 8) = make_int4(0, 0, 0, 0);
        }
        __syncthreads();

        // ---- GEMM2 in registers: S[16][64] = Q_tile @ K^T ----
        float s[32];                                   // 8 n-tiles x 4
        #pragma unroll
        for (int i = 0; i < 32; i++) s[i] = 0.0f;

        #pragma unroll
        for (int kt = 0; kt < 2; kt++) {               // d chunks of 16
            unsigned a0, a1, a2, a3;
            {
                int r = m * 16 + (lane & 7) + ((lane >> 3) & 1) * 8;
                int c = kt * 16 + (lane >> 4) * 8;
                ldsm4(a0, a1, a2, a3, smaddr(qh + r * 104 + c));
            }
            #pragma unroll
            for (int ng = 0; ng < 4; ng++) {           // token groups of 16
                unsigned b0, b1, b2, b3;
                int r = ng * 16 + (lane & 7) + (lane >> 4) * 8;
                int c = 32 + kt * 16 + ((lane >> 3) & 1) * 8;
                ldsm4(b0, b1, b2, b3, smaddr(qh + r * 104 + c));
                mma16816(s + (2 * ng) * 4,     a0, a1, a2, a3, b0, b1);
                mma16816(s + (2 * ng + 1) * 4, a0, a1, a2, a3, b2, b3);
            }
        }

        // ---- masked softmax in registers (rows rA = m*16+lane/4 and +8) ----
        float mxA = -1e30f, mxB = -1e30f;
        #pragma unroll
        for (int t = 0; t < 8; t++) {
            int c0 = 8 * t + q2;                       // even; pair never straddles 32
            unsigned vm = (c0 < 32) ? (mb0 >> c0) : (mb1 >> (c0 - 32));
            s[4 * t + 0] = (vm & 1) ? s[4 * t + 0] * SCALE_F : -1e30f;
            s[4 * t + 1] = (vm & 2) ? s[4 * t + 1] * SCALE_F : -1e30f;
            s[4 * t + 2] = (vm & 1) ? s[4 * t + 2] * SCALE_F : -1e30f;
            s[4 * t + 3] = (vm & 2) ? s[4 * t + 3] * SCALE_F : -1e30f;
            mxA = fmaxf(mxA, fmaxf(s[4 * t + 0], s[4 * t + 1]));
            mxB = fmaxf(mxB, fmaxf(s[4 * t + 2], s[4 * t + 3]));
        }
        mxA = fmaxf(mxA, __shfl_xor_sync(0xffffffffu, mxA, 1));
        mxA = fmaxf(mxA, __shfl_xor_sync(0xffffffffu, mxA, 2));
        mxB = fmaxf(mxB, __shfl_xor_sync(0xffffffffu, mxB, 1));
        mxB = fmaxf(mxB, __shfl_xor_sync(0xffffffffu, mxB, 2));

        float smA = 0.0f, smB = 0.0f;
        #pragma unroll
        for (int t = 0; t < 8; t++) {
            s[4 * t + 0] = __expf(s[4 * t + 0] - mxA);
            s[4 * t + 1] = __expf(s[4 * t + 1] - mxA);
            s[4 * t + 2] = __expf(s[4 * t + 2] - mxB);
            s[4 * t + 3] = __expf(s[4 * t + 3] - mxB);
            smA += s[4 * t + 0] + s[4 * t + 1];
            smB += s[4 * t + 2] + s[4 * t + 3];
        }
        smA += __shfl_xor_sync(0xffffffffu, smA, 1);
        smA += __shfl_xor_sync(0xffffffffu, smA, 2);
        smB += __shfl_xor_sync(0xffffffffu, smB, 1);
        smB += __shfl_xor_sync(0xffffffffu, smB, 2);
        const float invA = 1.0f / smA, invB = 1.0f / smB;

        // ---- P accumulator -> A-fragments (layout identity, no shuffles) ----
        unsigned pa[16];
        #pragma unroll
        for (int kc = 0; kc < 4; kc++) {
            float* t0 = s + (2 * kc) * 4;
            float* t1 = s + (2 * kc + 1) * 4;
            pa[4 * kc + 0] = pack_h2(t0[0] * invA, t0[1] * invA);
            pa[4 * kc + 1] = pack_h2(t0[2] * invB, t0[3] * invB);
            pa[4 * kc + 2] = pack_h2(t1[0] * invA, t1[1] * invA);
            pa[4 * kc + 3] = pack_h2(t1[2] * invB, t1[3] * invB);
        }

        // ---- GEMM3 in registers: O[16][32] = P @ V ----
        float o[16];
        #pragma unroll
        for (int i = 0; i < 16; i++) o[i] = 0.0f;
        #pragma unroll
        for (int kc = 0; kc < 4; kc++) {               // token chunks of 16
            #pragma unroll
            for (int nh = 0; nh < 2; nh++) {           // d halves of 16
                unsigned b0, b1, b2, b3;
                int r = kc * 16 + (lane & 7) + ((lane >> 3) & 1) * 8;
                int c = 64 + nh * 16 + (lane >> 4) * 8;
                ldsm4t(b0, b1, b2, b3, smaddr(qh + r * 104 + c));
                mma16816(o + (2 * nh) * 4,
                         pa[4 * kc + 0], pa[4 * kc + 1], pa[4 * kc + 2], pa[4 * kc + 3],
                         b0, b1);
                mma16816(o + (2 * nh + 1) * 4,
                         pa[4 * kc + 0], pa[4 * kc + 1], pa[4 * kc + 2], pa[4 * kc + 3],
                         b2, b3);
            }
        }

        // ---- store O tile to Oall (fp16) ----
        {
            int h  = hp * 2 + hh;
            int rA = m * 16 + (lane >> 2);
            #pragma unroll
            for (int t = 0; t < 4; t++) {
                int col = h * HDIM + 8 * t + q2;
                *(__half2*)(Oall + rA * 200 + col) =
                    __floats2half2_rn(o[4 * t + 0], o[4 * t + 1]);
                *(__half2*)(Oall + (rA + 8) * 200 + col) =
                    __floats2half2_rn(o[4 * t + 2], o[4 * t + 3]);
            }
        }
    }

    // ---- output projection: C[64][192] = Oall @ Wproj + bias (raw mma) ----
    // Wproj staged in 2 K-chunks of 96 rows per 96-col half.
    float* ob = out + (size_t)b * (NTOK * CDIM);
    const int rt = w >> 1;                 // row tile (16 rows)
    const int cq = w & 1;                  // 48-col quarter within the 96-col half

    #pragma unroll
    for (int hseg = 0; hseg < 2; hseg++) {
        float C[6][4];
        #pragma unroll
        for (int n = 0; n < 6; n++)
            #pragma unroll
            for (int e = 0; e < 4; e++) C[n][e] = 0.0f;

        #pragma unroll
        for (int kc2 = 0; kc2 < 2; kc2++) {           // K chunks of 96
            __syncthreads();   // prior reads of wp/qbuf2 (or attention O stores) done
            for (int i = tid; i < 1152; i += 256) {   // 96 rows * 12 int4
                int row = i / 12, v8 = i % 12;
                const int4* sp = (const int4*)(g_wproj + (kc2 * 96 + row) * 192 + hseg * 96 + v8 * 8);
                *(int4*)(wp + row * 104 + v8 * 8) = *sp;
            }
            __syncthreads();

            #pragma unroll
            for (int kt = 0; kt < 6; kt++) {
                unsigned a0, a1, a2, a3;
                {
                    int rA = rt * 16 + (lane & 7) + ((lane >> 3) & 1) * 8;
                    int cA = kc2 * 96 + kt * 16 + (lane >> 4) * 8;
                    ldsm4(a0, a1, a2, a3, smaddr(Oall + rA * 200 + cA));
                }
                int rB = kt * 16 + (lane & 7) + ((lane >> 3) & 1) * 8;
                #pragma unroll
                for (int np = 0; np < 3; np++) {
                    unsigned b0, b1, b2, b3;
                    int cB = cq * 48 + np * 16 + (lane >> 4) * 8;
                    ldsm4t(b0, b1, b2, b3, smaddr(wp + rB * 104 + cB));
                    mma16816(C[2 * np],     a0, a1, a2, a3, b0, b1);
                    mma16816(C[2 * np + 1], a0, a1, a2, a3, b2, b3);
                }
            }
        }

        // ---- epilogue: +bias, direct f32 stores, rows < 49 ----
        {
            int r = rt * 16 + (lane >> 2);
            #pragma unroll
            for (int n = 0; n < 6; n++) {
                int col = hseg * 96 + cq * 48 + 8 * n + q2;
                float2 bb = *(const float2*)(bproj + col);
                if (r < NTOK) {
                    ob[r * CDIM + col]     = C[n][0] + bb.x;
                    ob[r * CDIM + col + 1] = C[n][1] + bb.y;
                }
                if (r + 8 < NTOK) {
                    ob[(r + 8) * CDIM + col]     = C[n][2] + bb.x;
                    ob[(r + 8) * CDIM + col + 1] = C[n][3] + bb.y;
                }
            }
        }
    }
}

extern "C" void kernel_launch(void* const* d_in, const int* in_sizes, int n_in,
                              void* d_out, int out_size)
{
    (void)in_sizes; (void)n_in; (void)out_size;
    const float* x    = (const float*)d_in[0];
    const int*   mask = (const int*)  d_in[1];
    const float* wq   = (const float*)d_in[2];
    const float* bq   = (const float*)d_in[3];
    const float* wpj  = (const float*)d_in[4];
    const float* bp   = (const float*)d_in[5];
    float* out = (float*)d_out;

    conv_w<<<(CDIM * 3 * CDIM + 255) / 256, 256>>>(wq, wpj);

    cudaFuncSetAttribute(qkv_gemm, cudaFuncAttributeMaxDynamicSharedMemorySize, K1_SMEM);
    qkv_gemm<<<QKV_ROWS / 128, 256, K1_SMEM>>>(x, bq);

    cudaFuncSetAttribute(attn_proj, cudaFuncAttributeMaxDynamicSharedMemorySize, K2_SMEM);
    attn_proj<<<B_TOT, 256, K2_SMEM>>>(mask, bp, out);
}

// round 10
// speedup vs baseline: 1.0946x; 1.0946x over previous
#include <cstdint>
#include <stdint.h>
#include <cuda_runtime.h>
#include <cuda_fp16.h>

#define B_TOT   8192
#define NTOK    49
#define CDIM    192
#define NH      6
#define HDIM    32
#define SCALE_F 0.17677669529663687f   // 1/sqrt(32)
#define QKV_ROWS (B_TOT * NTOK)        // 401408

// fp16 copies of the weights (converted by conv_w each call; deterministic)
__device__ __align__(16) __half g_wqkv[CDIM * 3 * CDIM];   // [192][576] row-major
__device__ __align__(16) __half g_wproj[CDIM * CDIM];      // [192][192] row-major
// fp16 qkv scratch: [B_*N][576] row-major
__device__ __align__(16) __half g_qkv[QKV_ROWS * 3 * CDIM];

__global__ void conv_w(const float* __restrict__ wq, const float* __restrict__ wp) {
    int i = blockIdx.x * 256 + threadIdx.x;
    if (i < CDIM * 3 * CDIM) g_wqkv[i]  = __float2half_rn(wq[i]);
    if (i < CDIM * CDIM)     g_wproj[i] = __float2half_rn(wp[i]);
}

// ---------------------------------------------------------------------------
// raw-PTX helpers
// ---------------------------------------------------------------------------
__device__ __forceinline__ unsigned smaddr(const void* p) {
    return (unsigned)__cvta_generic_to_shared(p);
}
__device__ __forceinline__ void ldsm4(unsigned& r0, unsigned& r1, unsigned& r2, unsigned& r3,
                                      unsigned a) {
    asm volatile("ldmatrix.sync.aligned.m8n8.x4.shared.b16 {%0,%1,%2,%3}, [%4];"
                 : "=r"(r0), "=r"(r1), "=r"(r2), "=r"(r3) : "r"(a));
}
__device__ __forceinline__ void ldsm4t(unsigned& r0, unsigned& r1, unsigned& r2, unsigned& r3,
                                       unsigned a) {
    asm volatile("ldmatrix.sync.aligned.m8n8.x4.trans.shared.b16 {%0,%1,%2,%3}, [%4];"
                 : "=r"(r0), "=r"(r1), "=r"(r2), "=r"(r3) : "r"(a));
}
__device__ __forceinline__ void mma16816(float* c,
                                         unsigned a0, unsigned a1, unsigned a2, unsigned a3,
                                         unsigned b0, unsigned b1) {
    asm volatile(
        "mma.sync.aligned.m16n8k16.row.col.f32.f16.f16.f32 "
        "{%0,%1,%2,%3},{%4,%5,%6,%7},{%8,%9},{%0,%1,%2,%3};"
        : "+f"(c[0]), "+f"(c[1]), "+f"(c[2]), "+f"(c[3])
        : "r"(a0), "r"(a1), "r"(a2), "r"(a3), "r"(b0), "r"(b1));
}
__device__ __forceinline__ unsigned pack_h2(float a, float b) {
    __half2 h = __floats2half2_rn(a, b);
    return *(unsigned*)&h;
}
__device__ __forceinline__ void cp_async16(unsigned dst, const void* src) {
    asm volatile("cp.async.cg.shared.global [%0], [%1], 16;" :: "r"(dst), "l"(src));
}
__device__ __forceinline__ void cp_commit() {
    asm volatile("cp.async.commit_group;");
}
__device__ __forceinline__ void cp_wait0() {
    asm volatile("cp.async.wait_group 0;");
}

// ============================================================================
// Kernel 1: QKV projection GEMM, raw mma, double-buffered cp.async staging.
// Warp owns 16 rows; A (16x192) in registers; weight chunk nc+1 streamed in
// while computing chunk nc. smem: 2 x half[192][104] = 79872 B -> 2 CTAs/SM.
// ============================================================================
#define K1_SMEM 79872

__global__ void __launch_bounds__(256, 2)
qkv_gemm(const float* __restrict__ x, const float* __restrict__ bqkv)
{
    extern __shared__ __align__(128) char smem[];

    const int tid  = threadIdx.x;
    const int w    = tid >> 5;
    const int lane = tid & 31;
    const int rbase = blockIdx.x * 128 + w * 16;
    const int c0 = 2 * (lane & 3);

    // ---- issue staging of chunk 0 first so it overlaps the A loads ----
    {
        __half* wb = (__half*)smem;
        for (int i = tid; i < 2304; i += 256) {      // 192 rows * 12 int4
            int row = i / 12, v8 = i % 12;
            cp_async16(smaddr(wb + row * 104 + v8 * 8),
                       g_wqkv + row * 576 + v8 * 8);
        }
        cp_commit();
    }

    // ---- A-fragments straight from gmem (fp32 -> fp16), held across chunks ----
    unsigned A[12][4];
    {
        const int r0 = rbase + (lane >> 2);
        const float* xr0 = x + (size_t)r0 * CDIM;
        const float* xr8 = xr0 + 8 * CDIM;
        #pragma unroll
        for (int kt = 0; kt < 12; kt++) {
            int c = kt * 16 + c0;
            float2 v;
            v = *(const float2*)(xr0 + c);     A[kt][0] = pack_h2(v.x, v.y);
            v = *(const float2*)(xr8 + c);     A[kt][1] = pack_h2(v.x, v.y);
            v = *(const float2*)(xr0 + c + 8); A[kt][2] = pack_h2(v.x, v.y);
            v = *(const float2*)(xr8 + c + 8); A[kt][3] = pack_h2(v.x, v.y);
        }
    }

    cp_wait0();
    __syncthreads();

    const int orow = rbase + (lane >> 2);

    for (int nc = 0; nc < 6; nc++) {
        __half* wsc = (__half*)(smem + (nc & 1) * 39936);

        // ---- prefetch chunk nc+1 into the other buffer ----
        if (nc < 5) {
            __half* wb = (__half*)(smem + ((nc + 1) & 1) * 39936);
            for (int i = tid; i < 2304; i += 256) {
                int row = i / 12, v8 = i % 12;
                cp_async16(smaddr(wb + row * 104 + v8 * 8),
                           g_wqkv + row * 576 + (nc + 1) * 96 + v8 * 8);
            }
            cp_commit();
        }

        // ---- compute chunk nc ----
        float C[12][4];
        #pragma unroll
        for (int n = 0; n < 12; n++)
            #pragma unroll
            for (int e = 0; e < 4; e++) C[n][e] = 0.0f;

        #pragma unroll
        for (int kt = 0; kt < 12; kt++) {
            int rB = kt * 16 + (lane & 7) + ((lane >> 3) & 1) * 8;
            #pragma unroll
            for (int np = 0; np < 6; np++) {
                unsigned b0, b1, b2, b3;
                int cB = np * 16 + (lane >> 4) * 8;
                ldsm4t(b0, b1, b2, b3, smaddr(wsc + rB * 104 + cB));
                mma16816(C[2 * np],     A[kt][0], A[kt][1], A[kt][2], A[kt][3], b0, b1);
                mma16816(C[2 * np + 1], A[kt][0], A[kt][1], A[kt][2], A[kt][3], b2, b3);
            }
        }

        // ---- epilogue: +bias, fp16, direct global store ----
        {
            __half* g0 = g_qkv + (size_t)orow * 576 + nc * 96;
            __half* g8 = g0 + (size_t)8 * 576;
            #pragma unroll
            for (int n = 0; n < 12; n++) {
                int col = 8 * n + c0;
                float2 bb = *(const float2*)(bqkv + nc * 96 + col);
                *(__half2*)(g0 + col) = __floats2half2_rn(C[n][0] + bb.x, C[n][1] + bb.y);
                *(__half2*)(g8 + col) = __floats2half2_rn(C[n][2] + bb.x, C[n][3] + bb.y);
            }
        }

        // cp.async for nc+1 complete + all warps done computing nc
        // (barrier also guards WAR reuse of this buffer in iteration nc+2)
        if (nc < 5) {
            cp_wait0();
            __syncthreads();
        }
    }
}

// ============================================================================
// Kernel 2: fused attention + output projection, one CTA per batch item.
// (identical to the round-8 version: register-resident attention, 2 heads
// per phase, raw-mma projection; 65.6KB smem, 3 CTAs/SM, no reg cap abuse)
// ============================================================================
// smem: Oall  half [64][200]   @0      25600
//       qbuf2 half 2x[64][104] @25600  26624  (attention)   -> ends 52224
//       wp    half [192][104]  @25600  39936  (projection)  -> ends 65536
//       mbs   u32 [2]          @65536      8  -> total 65544 (pad to 65600)
#define K2_SMEM 65600

__global__ void __launch_bounds__(256, 3)
attn_proj(const int* __restrict__ mask, const float* __restrict__ bproj,
          float* __restrict__ out)
{
    extern __shared__ __align__(128) char smem[];
    __half*   Oall  = (__half*)(smem);               // ld 200
    __half*   qbuf2 = (__half*)(smem + 25600);       // 2 heads, each ld 104 (Q|K|V)
    __half*   wp    = (__half*)(smem + 25600);       // ld 104 (union w/ qbuf2)
    unsigned* mbs   = (unsigned*)(smem + 65536);

    const int b    = blockIdx.x;
    const int tid  = threadIdx.x;
    const int w    = tid >> 5;
    const int lane = tid & 31;
    const int q2   = 2 * (lane & 3);                 // col offset within 8-col tile

    // ---- mask -> 64-bit ballot in smem ----
    {
        int valid = 0;
        if (tid < 64) valid = (tid < NTOK) ? (mask[b * NTOK + tid] != 0) : 0;
        unsigned bal = __ballot_sync(0xffffffffu, valid);
        if (w < 2 && lane == 0) mbs[w] = bal;
    }
    __syncthreads();
    const unsigned mb0 = mbs[0], mb1 = mbs[1];

    const __half* qkv_b = g_qkv + (size_t)b * NTOK * 576;

    const int hh = w >> 2;                 // which head of the pair this warp works on
    const int m  = w & 3;                  // m-tile (16 q rows)
    __half* qh = qbuf2 + hh * 6656;        // 6656 halves = 13312 B per head buffer

    for (int hp = 0; hp < 3; hp++) {
        __syncthreads();   // prior pair's ldmatrix reads of qbuf2 complete

        // ---- stage 2 heads: qbuf[hx][64][96] = Q|K|V cols of head hp*2+hx ----
        for (int i = tid; i < 2 * NTOK * 12; i += 256) {
            int hx = i / (NTOK * 12);
            int j  = i - hx * (NTOK * 12);
            int row = j / 12, j12 = j % 12;
            int seg = j12 >> 2, hv = j12 & 3;
            int h = hp * 2 + hx;
            const int4* s = (const int4*)(qkv_b + row * 576 + seg * 192 + h * HDIM + hv * 8);
            *(int4*)(qbuf2 + hx * 6656 + row * 104 + seg * 32 + hv * 8) = *s;
        }
        for (int i = tid; i < 2 * 15 * 13; i += 256) {   // zero-pad rows 49..63
            int hx = i / 195, j = i - hx * 195;
            int r = 49 + j / 13, v8 = j % 13;
            *(int4*)(qbuf2 + hx * 6656 + r * 104 + v8 * 8) = make_int4(0, 0, 0, 0);
        }
        __syncthreads();

        // ---- GEMM2 in registers: S[16][64] = Q_tile @ K^T ----
        float s[32];                                   // 8 n-tiles x 4
        #pragma unroll
        for (int i = 0; i < 32; i++) s[i] = 0.0f;

        #pragma unroll
        for (int kt = 0; kt < 2; kt++) {               // d chunks of 16
            unsigned a0, a1, a2, a3;
            {
                int r = m * 16 + (lane & 7) + ((lane >> 3) & 1) * 8;
                int c = kt * 16 + (lane >> 4) * 8;
                ldsm4(a0, a1, a2, a3, smaddr(qh + r * 104 + c));
            }
            #pragma unroll
            for (int ng = 0; ng < 4; ng++) {           // token groups of 16
                unsigned b0, b1, b2, b3;
                int r = ng * 16 + (lane & 7) + (lane >> 4) * 8;
                int c = 32 + kt * 16 + ((lane >> 3) & 1) * 8;
                ldsm4(b0, b1, b2, b3, smaddr(qh + r * 104 + c));
                mma16816(s + (2 * ng) * 4,     a0, a1, a2, a3, b0, b1);
                mma16816(s + (2 * ng + 1) * 4, a0, a1, a2, a3, b2, b3);
            }
        }

        // ---- masked softmax in registers (rows rA = m*16+lane/4 and +8) ----
        float mxA = -1e30f, mxB = -1e30f;
        #pragma unroll
        for (int t = 0; t < 8; t++) {
            int c0 = 8 * t + q2;                       // even; pair never straddles 32
            unsigned vm = (c0 < 32) ? (mb0 >> c0) : (mb1 >> (c0 - 32));
            s[4 * t + 0] = (vm & 1) ? s[4 * t + 0] * SCALE_F : -1e30f;
            s[4 * t + 1] = (vm & 2) ? s[4 * t + 1] * SCALE_F : -1e30f;
            s[4 * t + 2] = (vm & 1) ? s[4 * t + 2] * SCALE_F : -1e30f;
            s[4 * t + 3] = (vm & 2) ? s[4 * t + 3] * SCALE_F : -1e30f;
            mxA = fmaxf(mxA, fmaxf(s[4 * t + 0], s[4 * t + 1]));
            mxB = fmaxf(mxB, fmaxf(s[4 * t + 2], s[4 * t + 3]));
        }
        mxA = fmaxf(mxA, __shfl_xor_sync(0xffffffffu, mxA, 1));
        mxA = fmaxf(mxA, __shfl_xor_sync(0xffffffffu, mxA, 2));
        mxB = fmaxf(mxB, __shfl_xor_sync(0xffffffffu, mxB, 1));
        mxB = fmaxf(mxB, __shfl_xor_sync(0xffffffffu, mxB, 2));

        float smA = 0.0f, smB = 0.0f;
        #pragma unroll
        for (int t = 0; t < 8; t++) {
            s[4 * t + 0] = __expf(s[4 * t + 0] - mxA);
            s[4 * t + 1] = __expf(s[4 * t + 1] - mxA);
            s[4 * t + 2] = __expf(s[4 * t + 2] - mxB);
            s[4 * t + 3] = __expf(s[4 * t + 3] - mxB);
            smA += s[4 * t + 0] + s[4 * t + 1];
            smB += s[4 * t + 2] + s[4 * t + 3];
        }
        smA += __shfl_xor_sync(0xffffffffu, smA, 1);
        smA += __shfl_xor_sync(0xffffffffu, smA, 2);
        smB += __shfl_xor_sync(0xffffffffu, smB, 1);
        smB += __shfl_xor_sync(0xffffffffu, smB, 2);
        const float invA = 1.0f / smA, invB = 1.0f / smB;

        // ---- P accumulator -> A-fragments (layout identity, no shuffles) ----
        unsigned pa[16];
        #pragma unroll
        for (int kc = 0; kc < 4; kc++) {
            float* t0 = s + (2 * kc) * 4;
            float* t1 = s + (2 * kc + 1) * 4;
            pa[4 * kc + 0] = pack_h2(t0[0] * invA, t0[1] * invA);
            pa[4 * kc + 1] = pack_h2(t0[2] * invB, t0[3] * invB);
            pa[4 * kc + 2] = pack_h2(t1[0] * invA, t1[1] * invA);
            pa[4 * kc + 3] = pack_h2(t1[2] * invB, t1[3] * invB);
        }

        // ---- GEMM3 in registers: O[16][32] = P @ V ----
        float o[16];
        #pragma unroll
        for (int i = 0; i < 16; i++) o[i] = 0.0f;
        #pragma unroll
        for (int kc = 0; kc < 4; kc++) {               // token chunks of 16
            #pragma unroll
            for (int nh = 0; nh < 2; nh++) {           // d halves of 16
                unsigned b0, b1, b2, b3;
                int r = kc * 16 + (lane & 7) + ((lane >> 3) & 1) * 8;
                int c = 64 + nh * 16 + (lane >> 4) * 8;
                ldsm4t(b0, b1, b2, b3, smaddr(qh + r * 104 + c));
                mma16816(o + (2 * nh) * 4,
                         pa[4 * kc + 0], pa[4 * kc + 1], pa[4 * kc + 2], pa[4 * kc + 3],
                         b0, b1);
                mma16816(o + (2 * nh + 1) * 4,
                         pa[4 * kc + 0], pa[4 * kc + 1], pa[4 * kc + 2], pa[4 * kc + 3],
                         b2, b3);
            }
        }

        // ---- store O tile to Oall (fp16) ----
        {
            int h  = hp * 2 + hh;
            int rA = m * 16 + (lane >> 2);
            #pragma unroll
            for (int t = 0; t < 4; t++) {
                int col = h * HDIM + 8 * t + q2;
                *(__half2*)(Oall + rA * 200 + col) =
                    __floats2half2_rn(o[4 * t + 0], o[4 * t + 1]);
                *(__half2*)(Oall + (rA + 8) * 200 + col) =
                    __floats2half2_rn(o[4 * t + 2], o[4 * t + 3]);
            }
        }
    }

    // ---- output projection: C[64][192] = Oall @ Wproj + bias (raw mma) ----
    float* ob = out + (size_t)b * (NTOK * CDIM);
    const int rt = w >> 1;                 // row tile (16 rows)
    const int cq = w & 1;                  // 48-col quarter within the 96-col half

    #pragma unroll
    for (int hseg = 0; hseg < 2; hseg++) {
        __syncthreads();   // attention O stores (hseg 0) / prior wp reads (hseg 1) done
        for (int i = tid; i < 2304; i += 256) {       // 192 rows * 12 int4
            int row = i / 12, v8 = i % 12;
            const int4* sp = (const int4*)(g_wproj + row * 192 + hseg * 96 + v8 * 8);
            *(int4*)(wp + row * 104 + v8 * 8) = *sp;
        }
        __syncthreads();

        float C[6][4];
        #pragma unroll
        for (int n = 0; n < 6; n++)
            #pragma unroll
            for (int e = 0; e < 4; e++) C[n][e] = 0.0f;

        #pragma unroll
        for (int kt = 0; kt < 12; kt++) {
            unsigned a0, a1, a2, a3;
            {
                int rA = rt * 16 + (lane & 7) + ((lane >> 3) & 1) * 8;
                int cA = kt * 16 + (lane >> 4) * 8;
                ldsm4(a0, a1, a2, a3, smaddr(Oall + rA * 200 + cA));
            }
            int rB = kt * 16 + (lane & 7) + ((lane >> 3) & 1) * 8;
            #pragma unroll
            for (int np = 0; np < 3; np++) {
                unsigned b0, b1, b2, b3;
                int cB = cq * 48 + np * 16 + (lane >> 4) * 8;
                ldsm4t(b0, b1, b2, b3, smaddr(wp + rB * 104 + cB));
                mma16816(C[2 * np],     a0, a1, a2, a3, b0, b1);
                mma16816(C[2 * np + 1], a0, a1, a2, a3, b2, b3);
            }
        }

        // ---- epilogue: +bias, direct f32 stores, rows < 49 ----
        {
            int r = rt * 16 + (lane >> 2);
            #pragma unroll
            for (int n = 0; n < 6; n++) {
                int col = hseg * 96 + cq * 48 + 8 * n + q2;
                float2 bb = *(const float2*)(bproj + col);
                if (r < NTOK) {
                    ob[r * CDIM + col]     = C[n][0] + bb.x;
                    ob[r * CDIM + col + 1] = C[n][1] + bb.y;
                }
                if (r + 8 < NTOK) {
                    ob[(r + 8) * CDIM + col]     = C[n][2] + bb.x;
                    ob[(r + 8) * CDIM + col + 1] = C[n][3] + bb.y;
                }
            }
        }
    }
}

extern "C" void kernel_launch(void* const* d_in, const int* in_sizes, int n_in,
                              void* d_out, int out_size)
{
    (void)in_sizes; (void)n_in; (void)out_size;
    const float* x    = (const float*)d_in[0];
    const int*   mask = (const int*)  d_in[1];
    const float* wq   = (const float*)d_in[2];
    const float* bq   = (const float*)d_in[3];
    const float* wpj  = (const float*)d_in[4];
    const float* bp   = (const float*)d_in[5];
    float* out = (float*)d_out;

    conv_w<<<(CDIM * 3 * CDIM + 255) / 256, 256>>>(wq, wpj);

    cudaFuncSetAttribute(qkv_gemm, cudaFuncAttributeMaxDynamicSharedMemorySize, K1_SMEM);
    qkv_gemm<<<QKV_ROWS / 128, 256, K1_SMEM>>>(x, bq);

    cudaFuncSetAttribute(attn_proj, cudaFuncAttributeMaxDynamicSharedMemorySize, K2_SMEM);
    attn_proj<<<B_TOT, 256, K2_SMEM>>>(mask, bp, out);
}

// round 11
// speedup vs baseline: 1.1658x; 1.0650x over previous
#include <cstdint>
#include <stdint.h>
#include <cuda_runtime.h>
#include <cuda_fp16.h>

#define B_TOT   8192
#define NTOK    49
#define CDIM    192
#define NH      6
#define HDIM    32
#define SCALE_F 0.17677669529663687f   // 1/sqrt(32)
#define QKV_ROWS (B_TOT * NTOK)        // 401408

// fp16 copies of the weights (converted by conv_w each call; deterministic)
__device__ __align__(16) __half g_wqkv[CDIM * 3 * CDIM];   // [192][576] row-major
__device__ __align__(16) __half g_wproj[CDIM * CDIM];      // [192][192] row-major
// fp16 qkv scratch: [B_*N][576] row-major
__device__ __align__(16) __half g_qkv[QKV_ROWS * 3 * CDIM];
// fp16 attention-output scratch: [B_*N][192] row-major
__device__ __align__(16) __half g_o[QKV_ROWS * CDIM];

__global__ void conv_w(const float* __restrict__ wq, const float* __restrict__ wp) {
    int i = blockIdx.x * 256 + threadIdx.x;
    if (i < CDIM * 3 * CDIM) g_wqkv[i]  = __float2half_rn(wq[i]);
    if (i < CDIM * CDIM)     g_wproj[i] = __float2half_rn(wp[i]);
}

// ---------------------------------------------------------------------------
// raw-PTX helpers
// ---------------------------------------------------------------------------
__device__ __forceinline__ unsigned smaddr(const void* p) {
    return (unsigned)__cvta_generic_to_shared(p);
}
__device__ __forceinline__ void ldsm4(unsigned& r0, unsigned& r1, unsigned& r2, unsigned& r3,
                                      unsigned a) {
    asm volatile("ldmatrix.sync.aligned.m8n8.x4.shared.b16 {%0,%1,%2,%3}, [%4];"
                 : "=r"(r0), "=r"(r1), "=r"(r2), "=r"(r3) : "r"(a));
}
__device__ __forceinline__ void ldsm4t(unsigned& r0, unsigned& r1, unsigned& r2, unsigned& r3,
                                       unsigned a) {
    asm volatile("ldmatrix.sync.aligned.m8n8.x4.trans.shared.b16 {%0,%1,%2,%3}, [%4];"
                 : "=r"(r0), "=r"(r1), "=r"(r2), "=r"(r3) : "r"(a));
}
__device__ __forceinline__ void mma16816(float* c,
                                         unsigned a0, unsigned a1, unsigned a2, unsigned a3,
                                         unsigned b0, unsigned b1) {
    asm volatile(
        "mma.sync.aligned.m16n8k16.row.col.f32.f16.f16.f32 "
        "{%0,%1,%2,%3},{%4,%5,%6,%7},{%8,%9},{%0,%1,%2,%3};"
        : "+f"(c[0]), "+f"(c[1]), "+f"(c[2]), "+f"(c[3])
        : "r"(a0), "r"(a1), "r"(a2), "r"(a3), "r"(b0), "r"(b1));
}
__device__ __forceinline__ unsigned pack_h2(float a, float b) {
    __half2 h = __floats2half2_rn(a, b);
    return *(unsigned*)&h;
}
__device__ __forceinline__ void cp_async16(unsigned dst, const void* src) {
    asm volatile("cp.async.cg.shared.global [%0], [%1], 16;" :: "r"(dst), "l"(src));
}
__device__ __forceinline__ void cp_commit() {
    asm volatile("cp.async.commit_group;");
}
__device__ __forceinline__ void cp_wait0() {
    asm volatile("cp.async.wait_group 0;");
}

// ============================================================================
// Kernel 1: QKV projection GEMM, raw mma, double-buffered cp.async staging.
// (unchanged from round 10 — 2 CTAs/SM, A register-resident)
// ============================================================================
#define K1_SMEM 79872

__global__ void __launch_bounds__(256, 2)
qkv_gemm(const float* __restrict__ x, const float* __restrict__ bqkv)
{
    extern __shared__ __align__(128) char smem[];

    const int tid  = threadIdx.x;
    const int w    = tid >> 5;
    const int lane = tid & 31;
    const int rbase = blockIdx.x * 128 + w * 16;
    const int c0 = 2 * (lane & 3);

    {
        __half* wb = (__half*)smem;
        for (int i = tid; i < 2304; i += 256) {      // 192 rows * 12 int4
            int row = i / 12, v8 = i % 12;
            cp_async16(smaddr(wb + row * 104 + v8 * 8),
                       g_wqkv + row * 576 + v8 * 8);
        }
        cp_commit();
    }

    unsigned A[12][4];
    {
        const int r0 = rbase + (lane >> 2);
        const float* xr0 = x + (size_t)r0 * CDIM;
        const float* xr8 = xr0 + 8 * CDIM;
        #pragma unroll
        for (int kt = 0; kt < 12; kt++) {
            int c = kt * 16 + c0;
            float2 v;
            v = *(const float2*)(xr0 + c);     A[kt][0] = pack_h2(v.x, v.y);
            v = *(const float2*)(xr8 + c);     A[kt][1] = pack_h2(v.x, v.y);
            v = *(const float2*)(xr0 + c + 8); A[kt][2] = pack_h2(v.x, v.y);
            v = *(const float2*)(xr8 + c + 8); A[kt][3] = pack_h2(v.x, v.y);
        }
    }

    cp_wait0();
    __syncthreads();

    const int orow = rbase + (lane >> 2);

    for (int nc = 0; nc < 6; nc++) {
        __half* wsc = (__half*)(smem + (nc & 1) * 39936);

        if (nc < 5) {
            __half* wb = (__half*)(smem + ((nc + 1) & 1) * 39936);
            for (int i = tid; i < 2304; i += 256) {
                int row = i / 12, v8 = i % 12;
                cp_async16(smaddr(wb + row * 104 + v8 * 8),
                           g_wqkv + row * 576 + (nc + 1) * 96 + v8 * 8);
            }
            cp_commit();
        }

        float C[12][4];
        #pragma unroll
        for (int n = 0; n < 12; n++)
            #pragma unroll
            for (int e = 0; e < 4; e++) C[n][e] = 0.0f;

        #pragma unroll
        for (int kt = 0; kt < 12; kt++) {
            int rB = kt * 16 + (lane & 7) + ((lane >> 3) & 1) * 8;
            #pragma unroll
            for (int np = 0; np < 6; np++) {
                unsigned b0, b1, b2, b3;
                int cB = np * 16 + (lane >> 4) * 8;
                ldsm4t(b0, b1, b2, b3, smaddr(wsc + rB * 104 + cB));
                mma16816(C[2 * np],     A[kt][0], A[kt][1], A[kt][2], A[kt][3], b0, b1);
                mma16816(C[2 * np + 1], A[kt][0], A[kt][1], A[kt][2], A[kt][3], b2, b3);
            }
        }

        {
            __half* g0 = g_qkv + (size_t)orow * 576 + nc * 96;
            __half* g8 = g0 + (size_t)8 * 576;
            #pragma unroll
            for (int n = 0; n < 12; n++) {
                int col = 8 * n + c0;
                float2 bb = *(const float2*)(bqkv + nc * 96 + col);
                *(__half2*)(g0 + col) = __floats2half2_rn(C[n][0] + bb.x, C[n][1] + bb.y);
                *(__half2*)(g8 + col) = __floats2half2_rn(C[n][2] + bb.x, C[n][3] + bb.y);
            }
        }

        if (nc < 5) {
            cp_wait0();
            __syncthreads();
        }
    }
}

// ============================================================================
// Kernel 2: attention ONLY, one CTA per batch item. Register-resident core
// (2 heads/phase); head-pair staging double-buffered with cp.async; O tiles
// stored directly to g_o scratch (fp16). No projection, no Oall smem.
// smem: qbufs 2 x 26624 = 53248 | mbs u32[2] @53248 -> 53264 total
// ============================================================================
#define K2_SMEM 53264

__global__ void __launch_bounds__(256, 3)
attn_only(const int* __restrict__ mask)
{
    extern __shared__ __align__(128) char smem[];
    __half*   qbufs = (__half*)(smem);               // 2 buffers x (2 heads x 6656 halves)
    unsigned* mbs   = (unsigned*)(smem + 53248);

    const int b    = blockIdx.x;
    const int tid  = threadIdx.x;
    const int w    = tid >> 5;
    const int lane = tid & 31;
    const int q2   = 2 * (lane & 3);

    const __half* qkv_b = g_qkv + (size_t)b * NTOK * 576;

    // ---- mask ballot, zero pad rows (both buffers), issue stage hp=0 ----
    {
        int valid = 0;
        if (tid < 64) valid = (tid < NTOK) ? (mask[b * NTOK + tid] != 0) : 0;
        unsigned bal = __ballot_sync(0xffffffffu, valid);
        if (w < 2 && lane == 0) mbs[w] = bal;
    }
    for (int i = tid; i < 4 * 15 * 13; i += 256) {   // 2 bufs x 2 heads x 15 rows x 13 int4
        int buf = i / 390, j = i % 390;
        int hx = j / 195, k = j % 195;
        int r = 49 + k / 13, v8 = k % 13;
        *(int4*)(qbufs + buf * 13312 + hx * 6656 + r * 104 + v8 * 8) = make_int4(0, 0, 0, 0);
    }
    for (int i = tid; i < 2 * NTOK * 12; i += 256) { // stage head pair 0 into buf 0
        int hx = i / (NTOK * 12);
        int j  = i - hx * (NTOK * 12);
        int row = j / 12, j12 = j % 12;
        int seg = j12 >> 2, hv = j12 & 3;
        cp_async16(smaddr(qbufs + hx * 6656 + row * 104 + seg * 32 + hv * 8),
                   qkv_b + row * 576 + seg * 192 + hx * HDIM + hv * 8);
    }
    cp_commit();

    const int hh = w >> 2;                 // head within pair
    const int m  = w & 3;                  // m-tile (16 q rows)

    for (int hp = 0; hp < 3; hp++) {
        cp_wait0();
        __syncthreads();   // buffer hp ready; compute hp-1 done (WAR for hp+1's buffer)
        const unsigned mb0 = mbs[0], mb1 = mbs[1];

        // ---- prefetch head pair hp+1 into the other buffer ----
        if (hp < 2) {
            __half* wb = qbufs + ((hp + 1) & 1) * 13312;
            for (int i = tid; i < 2 * NTOK * 12; i += 256) {
                int hx = i / (NTOK * 12);
                int j  = i - hx * (NTOK * 12);
                int row = j / 12, j12 = j % 12;
                int seg = j12 >> 2, hv = j12 & 3;
                int h = (hp + 1) * 2 + hx;
                cp_async16(smaddr(wb + hx * 6656 + row * 104 + seg * 32 + hv * 8),
                           qkv_b + row * 576 + seg * 192 + h * HDIM + hv * 8);
            }
            cp_commit();
        }

        __half* qh = qbufs + (hp & 1) * 13312 + hh * 6656;

        // ---- GEMM2 in registers: S[16][64] = Q_tile @ K^T ----
        float s[32];
        #pragma unroll
        for (int i = 0; i < 32; i++) s[i] = 0.0f;

        #pragma unroll
        for (int kt = 0; kt < 2; kt++) {
            unsigned a0, a1, a2, a3;
            {
                int r = m * 16 + (lane & 7) + ((lane >> 3) & 1) * 8;
                int c = kt * 16 + (lane >> 4) * 8;
                ldsm4(a0, a1, a2, a3, smaddr(qh + r * 104 + c));
            }
            #pragma unroll
            for (int ng = 0; ng < 4; ng++) {
                unsigned b0, b1, b2, b3;
                int r = ng * 16 + (lane & 7) + (lane >> 4) * 8;
                int c = 32 + kt * 16 + ((lane >> 3) & 1) * 8;
                ldsm4(b0, b1, b2, b3, smaddr(qh + r * 104 + c));
                mma16816(s + (2 * ng) * 4,     a0, a1, a2, a3, b0, b1);
                mma16816(s + (2 * ng + 1) * 4, a0, a1, a2, a3, b2, b3);
            }
        }

        // ---- masked softmax in registers ----
        float mxA = -1e30f, mxB = -1e30f;
        #pragma unroll
        for (int t = 0; t < 8; t++) {
            int c0 = 8 * t + q2;
            unsigned vm = (c0 < 32) ? (mb0 >> c0) : (mb1 >> (c0 - 32));
            s[4 * t + 0] = (vm & 1) ? s[4 * t + 0] * SCALE_F : -1e30f;
            s[4 * t + 1] = (vm & 2) ? s[4 * t + 1] * SCALE_F : -1e30f;
            s[4 * t + 2] = (vm & 1) ? s[4 * t + 2] * SCALE_F : -1e30f;
            s[4 * t + 3] = (vm & 2) ? s[4 * t + 3] * SCALE_F : -1e30f;
            mxA = fmaxf(mxA, fmaxf(s[4 * t + 0], s[4 * t + 1]));
            mxB = fmaxf(mxB, fmaxf(s[4 * t + 2], s[4 * t + 3]));
        }
        mxA = fmaxf(mxA, __shfl_xor_sync(0xffffffffu, mxA, 1));
        mxA = fmaxf(mxA, __shfl_xor_sync(0xffffffffu, mxA, 2));
        mxB = fmaxf(mxB, __shfl_xor_sync(0xffffffffu, mxB, 1));
        mxB = fmaxf(mxB, __shfl_xor_sync(0xffffffffu, mxB, 2));

        float smA = 0.0f, smB = 0.0f;
        #pragma unroll
        for (int t = 0; t < 8; t++) {
            s[4 * t + 0] = __expf(s[4 * t + 0] - mxA);
            s[4 * t + 1] = __expf(s[4 * t + 1] - mxA);
            s[4 * t + 2] = __expf(s[4 * t + 2] - mxB);
            s[4 * t + 3] = __expf(s[4 * t + 3] - mxB);
            smA += s[4 * t + 0] + s[4 * t + 1];
            smB += s[4 * t + 2] + s[4 * t + 3];
        }
        smA += __shfl_xor_sync(0xffffffffu, smA, 1);
        smA += __shfl_xor_sync(0xffffffffu, smA, 2);
        smB += __shfl_xor_sync(0xffffffffu, smB, 1);
        smB += __shfl_xor_sync(0xffffffffu, smB, 2);
        const float invA = 1.0f / smA, invB = 1.0f / smB;

        // ---- P accumulator -> A-fragments ----
        unsigned pa[16];
        #pragma unroll
        for (int kc = 0; kc < 4; kc++) {
            float* t0 = s + (2 * kc) * 4;
            float* t1 = s + (2 * kc + 1) * 4;
            pa[4 * kc + 0] = pack_h2(t0[0] * invA, t0[1] * invA);
            pa[4 * kc + 1] = pack_h2(t0[2] * invB, t0[3] * invB);
            pa[4 * kc + 2] = pack_h2(t1[0] * invA, t1[1] * invA);
            pa[4 * kc + 3] = pack_h2(t1[2] * invB, t1[3] * invB);
        }

        // ---- GEMM3: O[16][32] = P @ V ----
        float o[16];
        #pragma unroll
        for (int i = 0; i < 16; i++) o[i] = 0.0f;
        #pragma unroll
        for (int kc = 0; kc < 4; kc++) {
            #pragma unroll
            for (int nh = 0; nh < 2; nh++) {
                unsigned b0, b1, b2, b3;
                int r = kc * 16 + (lane & 7) + ((lane >> 3) & 1) * 8;
                int c = 64 + nh * 16 + (lane >> 4) * 8;
                ldsm4t(b0, b1, b2, b3, smaddr(qh + r * 104 + c));
                mma16816(o + (2 * nh) * 4,
                         pa[4 * kc + 0], pa[4 * kc + 1], pa[4 * kc + 2], pa[4 * kc + 3],
                         b0, b1);
                mma16816(o + (2 * nh + 1) * 4,
                         pa[4 * kc + 0], pa[4 * kc + 1], pa[4 * kc + 2], pa[4 * kc + 3],
                         b2, b3);
            }
        }

        // ---- store O tile directly to g_o scratch (fp16) ----
        {
            int h  = hp * 2 + hh;
            int rA = m * 16 + (lane >> 2);
            __half* r0p = g_o + ((size_t)b * NTOK + rA) * CDIM + h * HDIM;
            __half* r8p = r0p + (size_t)8 * CDIM;
            #pragma unroll
            for (int t = 0; t < 4; t++) {
                int col = 8 * t + q2;
                if (rA < NTOK)
                    *(__half2*)(r0p + col) = __floats2half2_rn(o[4 * t + 0], o[4 * t + 1]);
                if (rA + 8 < NTOK)
                    *(__half2*)(r8p + col) = __floats2half2_rn(o[4 * t + 2], o[4 * t + 3]);
            }
        }
    }
}

// ============================================================================
// Kernel 3: output projection GEMM. out[401408,192] = g_o @ Wproj + bias.
// K1-style: warp owns 16 rows; A-frags loaded directly from g_o (fp16 pairs,
// no conversion); both 96-col weight chunks staged once; f32 direct stores.
// smem: 2 x half[192][104] = 79872 -> 2 CTAs/SM.
// ============================================================================
#define K3_SMEM 79872

__global__ void __launch_bounds__(256, 2)
proj_gemm(const float* __restrict__ bproj, float* __restrict__ out)
{
    extern __shared__ __align__(128) char smem[];
    __half* wsc = (__half*)smem;                    // 2 chunks, stride 19968 halves

    const int tid  = threadIdx.x;
    const int w    = tid >> 5;
    const int lane = tid & 31;
    const int rbase = blockIdx.x * 128 + w * 16;
    const int c0 = 2 * (lane & 3);

    // ---- stage both weight chunks (cp.async, one group) ----
    for (int i = tid; i < 4608; i += 256) {          // 2 ch x 192 rows x 12 int4
        int ch = i / 2304, j = i % 2304;
        int row = j / 12, v8 = j % 12;
        cp_async16(smaddr(wsc + ch * 19968 + row * 104 + v8 * 8),
                   g_wproj + row * 192 + ch * 96 + v8 * 8);
    }
    cp_commit();

    // ---- A-fragments directly from g_o (already fp16 pairs) ----
    unsigned A[12][4];
    {
        const int r0 = rbase + (lane >> 2);
        const __half* or0 = g_o + (size_t)r0 * CDIM;
        const __half* or8 = or0 + 8 * CDIM;
        #pragma unroll
        for (int kt = 0; kt < 12; kt++) {
            int c = kt * 16 + c0;
            A[kt][0] = *(const unsigned*)(or0 + c);
            A[kt][1] = *(const unsigned*)(or8 + c);
            A[kt][2] = *(const unsigned*)(or0 + c + 8);
            A[kt][3] = *(const unsigned*)(or8 + c + 8);
        }
    }

    cp_wait0();
    __syncthreads();

    const int orow = rbase + (lane >> 2);

    #pragma unroll
    for (int ch = 0; ch < 2; ch++) {
        __half* wc = wsc + ch * 19968;

        float C[12][4];
        #pragma unroll
        for (int n = 0; n < 12; n++)
            #pragma unroll
            for (int e = 0; e < 4; e++) C[n][e] = 0.0f;

        #pragma unroll
        for (int kt = 0; kt < 12; kt++) {
            int rB = kt * 16 + (lane & 7) + ((lane >> 3) & 1) * 8;
            #pragma unroll
            for (int np = 0; np < 6; np++) {
                unsigned b0, b1, b2, b3;
                int cB = np * 16 + (lane >> 4) * 8;
                ldsm4t(b0, b1, b2, b3, smaddr(wc + rB * 104 + cB));
                mma16816(C[2 * np],     A[kt][0], A[kt][1], A[kt][2], A[kt][3], b0, b1);
                mma16816(C[2 * np + 1], A[kt][0], A[kt][1], A[kt][2], A[kt][3], b2, b3);
            }
        }

        // ---- epilogue: +bias, f32 direct stores (every row valid) ----
        {
            float* g0 = out + (size_t)orow * CDIM + ch * 96;
            float* g8 = g0 + (size_t)8 * CDIM;
            #pragma unroll
            for (int n = 0; n < 12; n++) {
                int col = 8 * n + c0;
                float2 bb = *(const float2*)(bproj + ch * 96 + col);
                g0[col]     = C[n][0] + bb.x;
                g0[col + 1] = C[n][1] + bb.y;
                g8[col]     = C[n][2] + bb.x;
                g8[col + 1] = C[n][3] + bb.y;
            }
        }
    }
}

extern "C" void kernel_launch(void* const* d_in, const int* in_sizes, int n_in,
                              void* d_out, int out_size)
{
    (void)in_sizes; (void)n_in; (void)out_size;
    const float* x    = (const float*)d_in[0];
    const int*   mask = (const int*)  d_in[1];
    const float* wq   = (const float*)d_in[2];
    const float* bq   = (const float*)d_in[3];
    const float* wpj  = (const float*)d_in[4];
    const float* bp   = (const float*)d_in[5];
    float* out = (float*)d_out;

    conv_w<<<(CDIM * 3 * CDIM + 255) / 256, 256>>>(wq, wpj);

    cudaFuncSetAttribute(qkv_gemm, cudaFuncAttributeMaxDynamicSharedMemorySize, K1_SMEM);
    qkv_gemm<<<QKV_ROWS / 128, 256, K1_SMEM>>>(x, bq);

    cudaFuncSetAttribute(attn_only, cudaFuncAttributeMaxDynamicSharedMemorySize, K2_SMEM);
    attn_only<<<B_TOT, 256, K2_SMEM>>>(mask);

    cudaFuncSetAttribute(proj_gemm, cudaFuncAttributeMaxDynamicSharedMemorySize, K3_SMEM);
    proj_gemm<<<QKV_ROWS / 128, 256, K3_SMEM>>>(bp, out);
}

// round 13
// speedup vs baseline: 1.2632x; 1.0835x over previous
#include <cstdint>
#include <stdint.h>
#include <cuda_runtime.h>
#include <cuda_fp16.h>

#define B_TOT   8192
#define NTOK    49
#define CDIM    192
#define NH      6
#define HDIM    32
#define SCALE_F 0.17677669529663687f   // 1/sqrt(32)
#define QKV_ROWS (B_TOT * NTOK)        // 401408

// fp16 copies of the weights (converted by conv_w each call; deterministic)
__device__ __align__(16) __half g_wqkv[CDIM * 3 * CDIM];   // [192][576] row-major
__device__ __align__(16) __half g_wproj[CDIM * CDIM];      // [192][192] row-major
// fp16 qkv scratch: [B_*N][576] row-major
__device__ __align__(16) __half g_qkv[QKV_ROWS * 3 * CDIM];
// fp16 attention-output scratch: [B_*N][192] row-major
__device__ __align__(16) __half g_o[QKV_ROWS * CDIM];

__global__ void conv_w(const float* __restrict__ wq, const float* __restrict__ wp) {
    int i = blockIdx.x * 256 + threadIdx.x;
    if (i < CDIM * 3 * CDIM) g_wqkv[i]  = __float2half_rn(wq[i]);
    if (i < CDIM * CDIM)     g_wproj[i] = __float2half_rn(wp[i]);
}

// ---------------------------------------------------------------------------
// raw-PTX helpers
// ---------------------------------------------------------------------------
__device__ __forceinline__ unsigned smaddr(const void* p) {
    return (unsigned)__cvta_generic_to_shared(p);
}
__device__ __forceinline__ void ldsm4(unsigned& r0, unsigned& r1, unsigned& r2, unsigned& r3,
                                      unsigned a) {
    asm volatile("ldmatrix.sync.aligned.m8n8.x4.shared.b16 {%0,%1,%2,%3}, [%4];"
                 : "=r"(r0), "=r"(r1), "=r"(r2), "=r"(r3) : "r"(a));
}
__device__ __forceinline__ void ldsm4t(unsigned& r0, unsigned& r1, unsigned& r2, unsigned& r3,
                                       unsigned a) {
    asm volatile("ldmatrix.sync.aligned.m8n8.x4.trans.shared.b16 {%0,%1,%2,%3}, [%4];"
                 : "=r"(r0), "=r"(r1), "=r"(r2), "=r"(r3) : "r"(a));
}
__device__ __forceinline__ void mma16816(float* c,
                                         unsigned a0, unsigned a1, unsigned a2, unsigned a3,
                                         unsigned b0, unsigned b1) {
    asm volatile(
        "mma.sync.aligned.m16n8k16.row.col.f32.f16.f16.f32 "
        "{%0,%1,%2,%3},{%4,%5,%6,%7},{%8,%9},{%0,%1,%2,%3};"
        : "+f"(c[0]), "+f"(c[1]), "+f"(c[2]), "+f"(c[3])
        : "r"(a0), "r"(a1), "r"(a2), "r"(a3), "r"(b0), "r"(b1));
}
__device__ __forceinline__ unsigned pack_h2(float a, float b) {
    __half2 h = __floats2half2_rn(a, b);
    return *(unsigned*)&h;
}
__device__ __forceinline__ void cp_async16(unsigned dst, const void* src) {
    asm volatile("cp.async.cg.shared.global [%0], [%1], 16;" :: "r"(dst), "l"(src));
}
__device__ __forceinline__ void cp_commit() {
    asm volatile("cp.async.commit_group;");
}
__device__ __forceinline__ void cp_wait0() {
    asm volatile("cp.async.wait_group 0;");
}

// ============================================================================
// Kernel 1: QKV projection GEMM, raw mma, double-buffered cp.async staging.
// (unchanged — 2 CTAs/SM, A register-resident)
// ============================================================================
#define K1_SMEM 79872

__global__ void __launch_bounds__(256, 2)
qkv_gemm(const float* __restrict__ x, const float* __restrict__ bqkv)
{
    extern __shared__ __align__(128) char smem[];

    const int tid  = threadIdx.x;
    const int w    = tid >> 5;
    const int lane = tid & 31;
    const int rbase = blockIdx.x * 128 + w * 16;
    const int c0 = 2 * (lane & 3);

    {
        __half* wb = (__half*)smem;
        for (int i = tid; i < 2304; i += 256) {      // 192 rows * 12 int4
            int row = i / 12, v8 = i % 12;
            cp_async16(smaddr(wb + row * 104 + v8 * 8),
                       g_wqkv + row * 576 + v8 * 8);
        }
        cp_commit();
    }

    unsigned A[12][4];
    {
        const int r0 = rbase + (lane >> 2);
        const float* xr0 = x + (size_t)r0 * CDIM;
        const float* xr8 = xr0 + 8 * CDIM;
        #pragma unroll
        for (int kt = 0; kt < 12; kt++) {
            int c = kt * 16 + c0;
            float2 v;
            v = *(const float2*)(xr0 + c);     A[kt][0] = pack_h2(v.x, v.y);
            v = *(const float2*)(xr8 + c);     A[kt][1] = pack_h2(v.x, v.y);
            v = *(const float2*)(xr0 + c + 8); A[kt][2] = pack_h2(v.x, v.y);
            v = *(const float2*)(xr8 + c + 8); A[kt][3] = pack_h2(v.x, v.y);
        }
    }

    cp_wait0();
    __syncthreads();

    const int orow = rbase + (lane >> 2);

    for (int nc = 0; nc < 6; nc++) {
        __half* wsc = (__half*)(smem + (nc & 1) * 39936);

        if (nc < 5) {
            __half* wb = (__half*)(smem + ((nc + 1) & 1) * 39936);
            for (int i = tid; i < 2304; i += 256) {
                int row = i / 12, v8 = i % 12;
                cp_async16(smaddr(wb + row * 104 + v8 * 8),
                           g_wqkv + row * 576 + (nc + 1) * 96 + v8 * 8);
            }
            cp_commit();
        }

        float C[12][4];
        #pragma unroll
        for (int n = 0; n < 12; n++)
            #pragma unroll
            for (int e = 0; e < 4; e++) C[n][e] = 0.0f;

        #pragma unroll
        for (int kt = 0; kt < 12; kt++) {
            int rB = kt * 16 + (lane & 7) + ((lane >> 3) & 1) * 8;
            #pragma unroll
            for (int np = 0; np < 6; np++) {
                unsigned b0, b1, b2, b3;
                int cB = np * 16 + (lane >> 4) * 8;
                ldsm4t(b0, b1, b2, b3, smaddr(wsc + rB * 104 + cB));
                mma16816(C[2 * np],     A[kt][0], A[kt][1], A[kt][2], A[kt][3], b0, b1);
                mma16816(C[2 * np + 1], A[kt][0], A[kt][1], A[kt][2], A[kt][3], b2, b3);
            }
        }

        {
            __half* g0 = g_qkv + (size_t)orow * 576 + nc * 96;
            __half* g8 = g0 + (size_t)8 * 576;
            #pragma unroll
            for (int n = 0; n < 12; n++) {
                int col = 8 * n + c0;
                float2 bb = *(const float2*)(bqkv + nc * 96 + col);
                *(__half2*)(g0 + col) = __floats2half2_rn(C[n][0] + bb.x, C[n][1] + bb.y);
                *(__half2*)(g8 + col) = __floats2half2_rn(C[n][2] + bb.x, C[n][3] + bb.y);
            }
        }

        if (nc < 5) {
            cp_wait0();
            __syncthreads();
        }
    }
}

// ============================================================================
// Kernel 2: attention ONLY, one CTA per batch item (unchanged — passing).
// ============================================================================
#define K2_SMEM 53264

__global__ void __launch_bounds__(256, 3)
attn_only(const int* __restrict__ mask)
{
    extern __shared__ __align__(128) char smem[];
    __half*   qbufs = (__half*)(smem);               // 2 buffers x (2 heads x 6656 halves)
    unsigned* mbs   = (unsigned*)(smem + 53248);

    const int b    = blockIdx.x;
    const int tid  = threadIdx.x;
    const int w    = tid >> 5;
    const int lane = tid & 31;
    const int q2   = 2 * (lane & 3);

    const __half* qkv_b = g_qkv + (size_t)b * NTOK * 576;

    {
        int valid = 0;
        if (tid < 64) valid = (tid < NTOK) ? (mask[b * NTOK + tid] != 0) : 0;
        unsigned bal = __ballot_sync(0xffffffffu, valid);
        if (w < 2 && lane == 0) mbs[w] = bal;
    }
    for (int i = tid; i < 4 * 15 * 13; i += 256) {
        int buf = i / 390, j = i % 390;
        int hx = j / 195, k = j % 195;
        int r = 49 + k / 13, v8 = k % 13;
        *(int4*)(qbufs + buf * 13312 + hx * 6656 + r * 104 + v8 * 8) = make_int4(0, 0, 0, 0);
    }
    for (int i = tid; i < 2 * NTOK * 12; i += 256) {
        int hx = i / (NTOK * 12);
        int j  = i - hx * (NTOK * 12);
        int row = j / 12, j12 = j % 12;
        int seg = j12 >> 2, hv = j12 & 3;
        cp_async16(smaddr(qbufs + hx * 6656 + row * 104 + seg * 32 + hv * 8),
                   qkv_b + row * 576 + seg * 192 + hx * HDIM + hv * 8);
    }
    cp_commit();

    const int hh = w >> 2;
    const int m  = w & 3;

    for (int hp = 0; hp < 3; hp++) {
        cp_wait0();
        __syncthreads();
        const unsigned mb0 = mbs[0], mb1 = mbs[1];

        if (hp < 2) {
            __half* wb = qbufs + ((hp + 1) & 1) * 13312;
            for (int i = tid; i < 2 * NTOK * 12; i += 256) {
                int hx = i / (NTOK * 12);
                int j  = i - hx * (NTOK * 12);
                int row = j / 12, j12 = j % 12;
                int seg = j12 >> 2, hv = j12 & 3;
                int h = (hp + 1) * 2 + hx;
                cp_async16(smaddr(wb + hx * 6656 + row * 104 + seg * 32 + hv * 8),
                           qkv_b + row * 576 + seg * 192 + h * HDIM + hv * 8);
            }
            cp_commit();
        }

        __half* qh = qbufs + (hp & 1) * 13312 + hh * 6656;

        float s[32];
        #pragma unroll
        for (int i = 0; i < 32; i++) s[i] = 0.0f;

        #pragma unroll
        for (int kt = 0; kt < 2; kt++) {
            unsigned a0, a1, a2, a3;
            {
                int r = m * 16 + (lane & 7) + ((lane >> 3) & 1) * 8;
                int c = kt * 16 + (lane >> 4) * 8;
                ldsm4(a0, a1, a2, a3, smaddr(qh + r * 104 + c));
            }
            #pragma unroll
            for (int ng = 0; ng < 4; ng++) {
                unsigned b0, b1, b2, b3;
                int r = ng * 16 + (lane & 7) + (lane >> 4) * 8;
                int c = 32 + kt * 16 + ((lane >> 3) & 1) * 8;
                ldsm4(b0, b1, b2, b3, smaddr(qh + r * 104 + c));
                mma16816(s + (2 * ng) * 4,     a0, a1, a2, a3, b0, b1);
                mma16816(s + (2 * ng + 1) * 4, a0, a1, a2, a3, b2, b3);
            }
        }

        float mxA = -1e30f, mxB = -1e30f;
        #pragma unroll
        for (int t = 0; t < 8; t++) {
            int c0 = 8 * t + q2;
            unsigned vm = (c0 < 32) ? (mb0 >> c0) : (mb1 >> (c0 - 32));
            s[4 * t + 0] = (vm & 1) ? s[4 * t + 0] * SCALE_F : -1e30f;
            s[4 * t + 1] = (vm & 2) ? s[4 * t + 1] * SCALE_F : -1e30f;
            s[4 * t + 2] = (vm & 1) ? s[4 * t + 2] * SCALE_F : -1e30f;
            s[4 * t + 3] = (vm & 2) ? s[4 * t + 3] * SCALE_F : -1e30f;
            mxA = fmaxf(mxA, fmaxf(s[4 * t + 0], s[4 * t + 1]));
            mxB = fmaxf(mxB, fmaxf(s[4 * t + 2], s[4 * t + 3]));
        }
        mxA = fmaxf(mxA, __shfl_xor_sync(0xffffffffu, mxA, 1));
        mxA = fmaxf(mxA, __shfl_xor_sync(0xffffffffu, mxA, 2));
        mxB = fmaxf(mxB, __shfl_xor_sync(0xffffffffu, mxB, 1));
        mxB = fmaxf(mxB, __shfl_xor_sync(0xffffffffu, mxB, 2));

        float smA = 0.0f, smB = 0.0f;
        #pragma unroll
        for (int t = 0; t < 8; t++) {
            s[4 * t + 0] = __expf(s[4 * t + 0] - mxA);
            s[4 * t + 1] = __expf(s[4 * t + 1] - mxA);
            s[4 * t + 2] = __expf(s[4 * t + 2] - mxB);
            s[4 * t + 3] = __expf(s[4 * t + 3] - mxB);
            smA += s[4 * t + 0] + s[4 * t + 1];
            smB += s[4 * t + 2] + s[4 * t + 3];
        }
        smA += __shfl_xor_sync(0xffffffffu, smA, 1);
        smA += __shfl_xor_sync(0xffffffffu, smA, 2);
        smB += __shfl_xor_sync(0xffffffffu, smB, 1);
        smB += __shfl_xor_sync(0xffffffffu, smB, 2);
        const float invA = 1.0f / smA, invB = 1.0f / smB;

        unsigned pa[16];
        #pragma unroll
        for (int kc = 0; kc < 4; kc++) {
            float* t0 = s + (2 * kc) * 4;
            float* t1 = s + (2 * kc + 1) * 4;
            pa[4 * kc + 0] = pack_h2(t0[0] * invA, t0[1] * invA);
            pa[4 * kc + 1] = pack_h2(t0[2] * invB, t0[3] * invB);
            pa[4 * kc + 2] = pack_h2(t1[0] * invA, t1[1] * invA);
            pa[4 * kc + 3] = pack_h2(t1[2] * invB, t1[3] * invB);
        }

        float o[16];
        #pragma unroll
        for (int i = 0; i < 16; i++) o[i] = 0.0f;
        #pragma unroll
        for (int kc = 0; kc < 4; kc++) {
            #pragma unroll
            for (int nh = 0; nh < 2; nh++) {
                unsigned b0, b1, b2, b3;
                int r = kc * 16 + (lane & 7) + ((lane >> 3) & 1) * 8;
                int c = 64 + nh * 16 + (lane >> 4) * 8;
                ldsm4t(b0, b1, b2, b3, smaddr(qh + r * 104 + c));
                mma16816(o + (2 * nh) * 4,
                         pa[4 * kc + 0], pa[4 * kc + 1], pa[4 * kc + 2], pa[4 * kc + 3],
                         b0, b1);
                mma16816(o + (2 * nh + 1) * 4,
                         pa[4 * kc + 0], pa[4 * kc + 1], pa[4 * kc + 2], pa[4 * kc + 3],
                         b2, b3);
            }
        }

        {
            int h  = hp * 2 + hh;
            int rA = m * 16 + (lane >> 2);
            __half* r0p = g_o + ((size_t)b * NTOK + rA) * CDIM + h * HDIM;
            __half* r8p = r0p + (size_t)8 * CDIM;
            #pragma unroll
            for (int t = 0; t < 4; t++) {
                int col = 8 * t + q2;
                if (rA < NTOK)
                    *(__half2*)(r0p + col) = __floats2half2_rn(o[4 * t + 0], o[4 * t + 1]);
                if (rA + 8 < NTOK)
                    *(__half2*)(r8p + col) = __floats2half2_rn(o[4 * t + 2], o[4 * t + 3]);
            }
        }
    }
}

// ============================================================================
// Kernel 3: output projection GEMM. out[401408,192] = g_o @ Wproj + bias.
// CTA = 128 rows (grid 3136), processed as 2 sub-blocks of 64 rows. Weights
// (both 96-col chunks, 79872 B) staged once. A sub-block staged via coalesced
// cp.async into abuf [64][200] (@ byte 79872, NO aliasing), A-frags via ldsm4.
// Warp = (m-tile w&3, col-half w>>2). Sub-block 1 staging overlaps sub-block
// 0 compute. smem total 105472 -> 2 CTAs/SM.
// ============================================================================
#define K3_SMEM 105472

__global__ void __launch_bounds__(256, 2)
proj_gemm(const float* __restrict__ bproj, float* __restrict__ out)
{
    extern __shared__ __align__(128) char smem[];
    __half* wsc  = (__half*)smem;                   // 2 chunks, stride 19968 halves
    __half* abuf = (__half*)(smem + 79872);         // [64][200] halves

    const int tid  = threadIdx.x;
    const int w    = tid >> 5;
    const int lane = tid & 31;
    const int rbase0 = blockIdx.x * 128;
    const int c0 = 2 * (lane & 3);
    const int mt = w & 3;                            // m-tile within 64-row sub-block
    const int ch = w >> 2;                           // 96-col half

    // ---- stage both weight chunks + A sub-block 0 (one cp.async group) ----
    for (int i = tid; i < 4608; i += 256) {          // 2 ch x 192 rows x 12 int4
        int cc = i / 2304, j = i % 2304;
        int row = j / 12, v8 = j % 12;
        cp_async16(smaddr(wsc + cc * 19968 + row * 104 + v8 * 8),
                   g_wproj + row * 192 + cc * 96 + v8 * 8);
    }
    for (int i = tid; i < 1536; i += 256) {          // 64 rows x 24 int4
        int row = i / 24, v8 = i % 24;
        cp_async16(smaddr(abuf + row * 200 + v8 * 8),
                   g_o + (size_t)(rbase0 + row) * CDIM + v8 * 8);
    }
    cp_commit();
    cp_wait0();
    __syncthreads();

    __half* wc = wsc + ch * 19968;

    #pragma unroll
    for (int blk = 0; blk < 2; blk++) {
        // ---- A-fragments from abuf via ldsm4 (row stride 400B) ----
        unsigned A[12][4];
        {
            int r = mt * 16 + (lane & 7) + ((lane >> 3) & 1) * 8;
            #pragma unroll
            for (int kt = 0; kt < 12; kt++) {
                int c = kt * 16 + (lane >> 4) * 8;
                ldsm4(A[kt][0], A[kt][1], A[kt][2], A[kt][3],
                      smaddr(abuf + r * 200 + c));
            }
        }
        __syncthreads();   // all warps done reading abuf

        // ---- overlap: stage sub-block 1 while computing sub-block 0 ----
        if (blk == 0) {
            for (int i = tid; i < 1536; i += 256) {
                int row = i / 24, v8 = i % 24;
                cp_async16(smaddr(abuf + row * 200 + v8 * 8),
                           g_o + (size_t)(rbase0 + 64 + row) * CDIM + v8 * 8);
            }
            cp_commit();
        }

        float C[12][4];
        #pragma unroll
        for (int n = 0; n < 12; n++)
            #pragma unroll
            for (int e = 0; e < 4; e++) C[n][e] = 0.0f;

        #pragma unroll
        for (int kt = 0; kt < 12; kt++) {
            int rB = kt * 16 + (lane & 7) + ((lane >> 3) & 1) * 8;
            #pragma unroll
            for (int np = 0; np < 6; np++) {
                unsigned b0, b1, b2, b3;
                int cB = np * 16 + (lane >> 4) * 8;
                ldsm4t(b0, b1, b2, b3, smaddr(wc + rB * 104 + cB));
                mma16816(C[2 * np],     A[kt][0], A[kt][1], A[kt][2], A[kt][3], b0, b1);
                mma16816(C[2 * np + 1], A[kt][0], A[kt][1], A[kt][2], A[kt][3], b2, b3);
            }
        }

        // ---- epilogue: +bias, float2 direct stores ----
        {
            int orow = rbase0 + blk * 64 + mt * 16 + (lane >> 2);
            float* g0 = out + (size_t)orow * CDIM + ch * 96;
            float* g8 = g0 + (size_t)8 * CDIM;
            #pragma unroll
            for (int n = 0; n < 12; n++) {
                int col = 8 * n + c0;
                float2 bb = *(const float2*)(bproj + ch * 96 + col);
                *(float2*)(g0 + col) = make_float2(C[n][0] + bb.x, C[n][1] + bb.y);
                *(float2*)(g8 + col) = make_float2(C[n][2] + bb.x, C[n][3] + bb.y);
            }
        }

        if (blk == 0) {
            cp_wait0();
            __syncthreads();   // abuf now holds sub-block 1
        }
    }
}

extern "C" void kernel_launch(void* const* d_in, const int* in_sizes, int n_in,
                              void* d_out, int out_size)
{
    (void)in_sizes; (void)n_in; (void)out_size;
    const float* x    = (const float*)d_in[0];
    const int*   mask = (const int*)  d_in[1];
    const float* wq   = (const float*)d_in[2];
    const float* bq   = (const float*)d_in[3];
    const float* wpj  = (const float*)d_in[4];
    const float* bp   = (const float*)d_in[5];
    float* out = (float*)d_out;

    conv_w<<<(CDIM * 3 * CDIM + 255) / 256, 256>>>(wq, wpj);

    cudaFuncSetAttribute(qkv_gemm, cudaFuncAttributeMaxDynamicSharedMemorySize, K1_SMEM);
    qkv_gemm<<<QKV_ROWS / 128, 256, K1_SMEM>>>(x, bq);

    cudaFuncSetAttribute(attn_only, cudaFuncAttributeMaxDynamicSharedMemorySize, K2_SMEM);
    attn_only<<<B_TOT, 256, K2_SMEM>>>(mask);

    cudaFuncSetAttribute(proj_gemm, cudaFuncAttributeMaxDynamicSharedMemorySize, K3_SMEM);
    proj_gemm<<<QKV_ROWS / 128, 256, K3_SMEM>>>(bp, out);
}

// round 14
// speedup vs baseline: 1.3076x; 1.0351x over previous
#include <cstdint>
#include <stdint.h>
#include <cuda_runtime.h>
#include <cuda_fp16.h>

#define B_TOT   8192
#define NTOK    49
#define CDIM    192
#define NH      6
#define HDIM    32
#define SCALE_F 0.17677669529663687f   // 1/sqrt(32)
#define QKV_ROWS (B_TOT * NTOK)        // 401408

// fp16 copies of the weights (converted by conv_w each call; deterministic)
__device__ __align__(16) __half g_wqkv[CDIM * 3 * CDIM];   // [192][576] row-major
__device__ __align__(16) __half g_wproj[CDIM * CDIM];      // [192][192] row-major
// fp16 qkv scratch: [B_*N][576] row-major
__device__ __align__(16) __half g_qkv[QKV_ROWS * 3 * CDIM];
// fp16 attention-output scratch: [B_*N][192] row-major
__device__ __align__(16) __half g_o[QKV_ROWS * CDIM];

__global__ void conv_w(const float* __restrict__ wq, const float* __restrict__ wp) {
    int i = blockIdx.x * 256 + threadIdx.x;
    if (i < CDIM * 3 * CDIM) g_wqkv[i]  = __float2half_rn(wq[i]);
    if (i < CDIM * CDIM)     g_wproj[i] = __float2half_rn(wp[i]);
}

// ---------------------------------------------------------------------------
// raw-PTX helpers
// ---------------------------------------------------------------------------
__device__ __forceinline__ unsigned smaddr(const void* p) {
    return (unsigned)__cvta_generic_to_shared(p);
}
__device__ __forceinline__ void ldsm4(unsigned& r0, unsigned& r1, unsigned& r2, unsigned& r3,
                                      unsigned a) {
    asm volatile("ldmatrix.sync.aligned.m8n8.x4.shared.b16 {%0,%1,%2,%3}, [%4];"
                 : "=r"(r0), "=r"(r1), "=r"(r2), "=r"(r3) : "r"(a));
}
__device__ __forceinline__ void ldsm4t(unsigned& r0, unsigned& r1, unsigned& r2, unsigned& r3,
                                       unsigned a) {
    asm volatile("ldmatrix.sync.aligned.m8n8.x4.trans.shared.b16 {%0,%1,%2,%3}, [%4];"
                 : "=r"(r0), "=r"(r1), "=r"(r2), "=r"(r3) : "r"(a));
}
__device__ __forceinline__ void mma16816(float* c,
                                         unsigned a0, unsigned a1, unsigned a2, unsigned a3,
                                         unsigned b0, unsigned b1) {
    asm volatile(
        "mma.sync.aligned.m16n8k16.row.col.f32.f16.f16.f32 "
        "{%0,%1,%2,%3},{%4,%5,%6,%7},{%8,%9},{%0,%1,%2,%3};"
        : "+f"(c[0]), "+f"(c[1]), "+f"(c[2]), "+f"(c[3])
        : "r"(a0), "r"(a1), "r"(a2), "r"(a3), "r"(b0), "r"(b1));
}
__device__ __forceinline__ unsigned pack_h2(float a, float b) {
    __half2 h = __floats2half2_rn(a, b);
    return *(unsigned*)&h;
}
__device__ __forceinline__ void cp_async16(unsigned dst, const void* src) {
    asm volatile("cp.async.cg.shared.global [%0], [%1], 16;" :: "r"(dst), "l"(src));
}
__device__ __forceinline__ void cp_commit() {
    asm volatile("cp.async.commit_group;");
}
__device__ __forceinline__ void cp_wait0() {
    asm volatile("cp.async.wait_group 0;");
}

// ============================================================================
// Kernel 1: QKV projection GEMM, raw mma, double-buffered cp.async staging.
// (unchanged — at its DRAM floor)
// ============================================================================
#define K1_SMEM 79872

__global__ void __launch_bounds__(256, 2)
qkv_gemm(const float* __restrict__ x, const float* __restrict__ bqkv)
{
    extern __shared__ __align__(128) char smem[];

    const int tid  = threadIdx.x;
    const int w    = tid >> 5;
    const int lane = tid & 31;
    const int rbase = blockIdx.x * 128 + w * 16;
    const int c0 = 2 * (lane & 3);

    {
        __half* wb = (__half*)smem;
        for (int i = tid; i < 2304; i += 256) {      // 192 rows * 12 int4
            int row = i / 12, v8 = i % 12;
            cp_async16(smaddr(wb + row * 104 + v8 * 8),
                       g_wqkv + row * 576 + v8 * 8);
        }
        cp_commit();
    }

    unsigned A[12][4];
    {
        const int r0 = rbase + (lane >> 2);
        const float* xr0 = x + (size_t)r0 * CDIM;
        const float* xr8 = xr0 + 8 * CDIM;
        #pragma unroll
        for (int kt = 0; kt < 12; kt++) {
            int c = kt * 16 + c0;
            float2 v;
            v = *(const float2*)(xr0 + c);     A[kt][0] = pack_h2(v.x, v.y);
            v = *(const float2*)(xr8 + c);     A[kt][1] = pack_h2(v.x, v.y);
            v = *(const float2*)(xr0 + c + 8); A[kt][2] = pack_h2(v.x, v.y);
            v = *(const float2*)(xr8 + c + 8); A[kt][3] = pack_h2(v.x, v.y);
        }
    }

    cp_wait0();
    __syncthreads();

    const int orow = rbase + (lane >> 2);

    for (int nc = 0; nc < 6; nc++) {
        __half* wsc = (__half*)(smem + (nc & 1) * 39936);

        if (nc < 5) {
            __half* wb = (__half*)(smem + ((nc + 1) & 1) * 39936);
            for (int i = tid; i < 2304; i += 256) {
                int row = i / 12, v8 = i % 12;
                cp_async16(smaddr(wb + row * 104 + v8 * 8),
                           g_wqkv + row * 576 + (nc + 1) * 96 + v8 * 8);
            }
            cp_commit();
        }

        float C[12][4];
        #pragma unroll
        for (int n = 0; n < 12; n++)
            #pragma unroll
            for (int e = 0; e < 4; e++) C[n][e] = 0.0f;

        #pragma unroll
        for (int kt = 0; kt < 12; kt++) {
            int rB = kt * 16 + (lane & 7) + ((lane >> 3) & 1) * 8;
            #pragma unroll
            for (int np = 0; np < 6; np++) {
                unsigned b0, b1, b2, b3;
                int cB = np * 16 + (lane >> 4) * 8;
                ldsm4t(b0, b1, b2, b3, smaddr(wsc + rB * 104 + cB));
                mma16816(C[2 * np],     A[kt][0], A[kt][1], A[kt][2], A[kt][3], b0, b1);
                mma16816(C[2 * np + 1], A[kt][0], A[kt][1], A[kt][2], A[kt][3], b2, b3);
            }
        }

        {
            __half* g0 = g_qkv + (size_t)orow * 576 + nc * 96;
            __half* g8 = g0 + (size_t)8 * 576;
            #pragma unroll
            for (int n = 0; n < 12; n++) {
                int col = 8 * n + c0;
                float2 bb = *(const float2*)(bqkv + nc * 96 + col);
                *(__half2*)(g0 + col) = __floats2half2_rn(C[n][0] + bb.x, C[n][1] + bb.y);
                *(__half2*)(g8 + col) = __floats2half2_rn(C[n][2] + bb.x, C[n][3] + bb.y);
            }
        }

        if (nc < 5) {
            cp_wait0();
            __syncthreads();
        }
    }
}

// ============================================================================
// Kernel 2: attention ONLY, one CTA per batch item.
// NEW: full qkv block (49x576) staged ONCE, coalesced (full-line DRAM reads).
// Row stride 584 halves -> conflict-free ldsm slicing of Q/K/V per head.
// Head loop is BARRIER-FREE (smem read-only after the single load sync).
// smem: qs half[64][584] = 74752 | mbs u32[2] @74752 -> 74768 total
// ============================================================================
#define K2_SMEM 74768

__global__ void __launch_bounds__(256, 3)
attn_only(const int* __restrict__ mask)
{
    extern __shared__ __align__(128) char smem[];
    __half*   qs  = (__half*)(smem);                 // ld 584 (Q:0-191 K:192-383 V:384-575)
    unsigned* mbs = (unsigned*)(smem + 74752);

    const int b    = blockIdx.x;
    const int tid  = threadIdx.x;
    const int w    = tid >> 5;
    const int lane = tid & 31;
    const int q2   = 2 * (lane & 3);

    const __half* qkv_b = g_qkv + (size_t)b * NTOK * 576;

    // ---- mask ballot ----
    {
        int valid = 0;
        if (tid < 64) valid = (tid < NTOK) ? (mask[b * NTOK + tid] != 0) : 0;
        unsigned bal = __ballot_sync(0xffffffffu, valid);
        if (w < 2 && lane == 0) mbs[w] = bal;
    }
    // ---- zero pad rows 49..63 (full width) ----
    for (int i = tid; i < 15 * 73; i += 256) {
        int r = 49 + i / 73, v8 = i % 73;
        *(int4*)(qs + r * 584 + v8 * 8) = make_int4(0, 0, 0, 0);
    }
    // ---- coalesced full-row staging: 49 rows x 72 int4 ----
    for (int i = tid; i < NTOK * 72; i += 256) {
        int row = i / 72, v8 = i % 72;
        cp_async16(smaddr(qs + row * 584 + v8 * 8), qkv_b + row * 576 + v8 * 8);
    }
    cp_commit();
    cp_wait0();
    __syncthreads();      // the ONLY barrier; qs is read-only from here on

    const unsigned mb0 = mbs[0], mb1 = mbs[1];
    const int hh = w >> 2;                 // head within pair
    const int m  = w & 3;                  // m-tile (16 q rows)

    #pragma unroll
    for (int hp = 0; hp < 3; hp++) {
        const int h  = hp * 2 + hh;
        const int qo = h * HDIM;           // Q col base
        const int ko = CDIM + h * HDIM;    // K col base
        const int vo = 2 * CDIM + h * HDIM;// V col base

        // ---- GEMM2 in registers: S[16][64] = Q_tile @ K^T ----
        float s[32];
        #pragma unroll
        for (int i = 0; i < 32; i++) s[i] = 0.0f;

        #pragma unroll
        for (int kt = 0; kt < 2; kt++) {
            unsigned a0, a1, a2, a3;
            {
                int r = m * 16 + (lane & 7) + ((lane >> 3) & 1) * 8;
                int c = qo + kt * 16 + (lane >> 4) * 8;
                ldsm4(a0, a1, a2, a3, smaddr(qs + r * 584 + c));
            }
            #pragma unroll
            for (int ng = 0; ng < 4; ng++) {
                unsigned b0, b1, b2, b3;
                int r = ng * 16 + (lane & 7) + (lane >> 4) * 8;
                int c = ko + kt * 16 + ((lane >> 3) & 1) * 8;
                ldsm4(b0, b1, b2, b3, smaddr(qs + r * 584 + c));
                mma16816(s + (2 * ng) * 4,     a0, a1, a2, a3, b0, b1);
                mma16816(s + (2 * ng + 1) * 4, a0, a1, a2, a3, b2, b3);
            }
        }

        // ---- masked softmax in registers ----
        float mxA = -1e30f, mxB = -1e30f;
        #pragma unroll
        for (int t = 0; t < 8; t++) {
            int c0 = 8 * t + q2;
            unsigned vm = (c0 < 32) ? (mb0 >> c0) : (mb1 >> (c0 - 32));
            s[4 * t + 0] = (vm & 1) ? s[4 * t + 0] * SCALE_F : -1e30f;
            s[4 * t + 1] = (vm & 2) ? s[4 * t + 1] * SCALE_F : -1e30f;
            s[4 * t + 2] = (vm & 1) ? s[4 * t + 2] * SCALE_F : -1e30f;
            s[4 * t + 3] = (vm & 2) ? s[4 * t + 3] * SCALE_F : -1e30f;
            mxA = fmaxf(mxA, fmaxf(s[4 * t + 0], s[4 * t + 1]));
            mxB = fmaxf(mxB, fmaxf(s[4 * t + 2], s[4 * t + 3]));
        }
        mxA = fmaxf(mxA, __shfl_xor_sync(0xffffffffu, mxA, 1));
        mxA = fmaxf(mxA, __shfl_xor_sync(0xffffffffu, mxA, 2));
        mxB = fmaxf(mxB, __shfl_xor_sync(0xffffffffu, mxB, 1));
        mxB = fmaxf(mxB, __shfl_xor_sync(0xffffffffu, mxB, 2));

        float smA = 0.0f, smB = 0.0f;
        #pragma unroll
        for (int t = 0; t < 8; t++) {
            s[4 * t + 0] = __expf(s[4 * t + 0] - mxA);
            s[4 * t + 1] = __expf(s[4 * t + 1] - mxA);
            s[4 * t + 2] = __expf(s[4 * t + 2] - mxB);
            s[4 * t + 3] = __expf(s[4 * t + 3] - mxB);
            smA += s[4 * t + 0] + s[4 * t + 1];
            smB += s[4 * t + 2] + s[4 * t + 3];
        }
        smA += __shfl_xor_sync(0xffffffffu, smA, 1);
        smA += __shfl_xor_sync(0xffffffffu, smA, 2);
        smB += __shfl_xor_sync(0xffffffffu, smB, 1);
        smB += __shfl_xor_sync(0xffffffffu, smB, 2);
        const float invA = 1.0f / smA, invB = 1.0f / smB;

        // ---- P accumulator -> A-fragments ----
        unsigned pa[16];
        #pragma unroll
        for (int kc = 0; kc < 4; kc++) {
            float* t0 = s + (2 * kc) * 4;
            float* t1 = s + (2 * kc + 1) * 4;
            pa[4 * kc + 0] = pack_h2(t0[0] * invA, t0[1] * invA);
            pa[4 * kc + 1] = pack_h2(t0[2] * invB, t0[3] * invB);
            pa[4 * kc + 2] = pack_h2(t1[0] * invA, t1[1] * invA);
            pa[4 * kc + 3] = pack_h2(t1[2] * invB, t1[3] * invB);
        }

        // ---- GEMM3: O[16][32] = P @ V ----
        float o[16];
        #pragma unroll
        for (int i = 0; i < 16; i++) o[i] = 0.0f;
        #pragma unroll
        for (int kc = 0; kc < 4; kc++) {
            #pragma unroll
            for (int nh = 0; nh < 2; nh++) {
                unsigned b0, b1, b2, b3;
                int r = kc * 16 + (lane & 7) + ((lane >> 3) & 1) * 8;
                int c = vo + nh * 16 + (lane >> 4) * 8;
                ldsm4t(b0, b1, b2, b3, smaddr(qs + r * 584 + c));
                mma16816(o + (2 * nh) * 4,
                         pa[4 * kc + 0], pa[4 * kc + 1], pa[4 * kc + 2], pa[4 * kc + 3],
                         b0, b1);
                mma16816(o + (2 * nh + 1) * 4,
                         pa[4 * kc + 0], pa[4 * kc + 1], pa[4 * kc + 2], pa[4 * kc + 3],
                         b2, b3);
            }
        }

        // ---- store O tile directly to g_o scratch (fp16) ----
        {
            int rA = m * 16 + (lane >> 2);
            __half* r0p = g_o + ((size_t)b * NTOK + rA) * CDIM + h * HDIM;
            __half* r8p = r0p + (size_t)8 * CDIM;
            #pragma unroll
            for (int t = 0; t < 4; t++) {
                int col = 8 * t + q2;
                if (rA < NTOK)
                    *(__half2*)(r0p + col) = __floats2half2_rn(o[4 * t + 0], o[4 * t + 1]);
                if (rA + 8 < NTOK)
                    *(__half2*)(r8p + col) = __floats2half2_rn(o[4 * t + 2], o[4 * t + 3]);
            }
        }
    }
}

// ============================================================================
// Kernel 3: output projection GEMM (unchanged — at its DRAM floor).
// ============================================================================
#define K3_SMEM 105472

__global__ void __launch_bounds__(256, 2)
proj_gemm(const float* __restrict__ bproj, float* __restrict__ out)
{
    extern __shared__ __align__(128) char smem[];
    __half* wsc  = (__half*)smem;                   // 2 chunks, stride 19968 halves
    __half* abuf = (__half*)(smem + 79872);         // [64][200] halves

    const int tid  = threadIdx.x;
    const int w    = tid >> 5;
    const int lane = tid & 31;
    const int rbase0 = blockIdx.x * 128;
    const int c0 = 2 * (lane & 3);
    const int mt = w & 3;                            // m-tile within 64-row sub-block
    const int ch = w >> 2;                           // 96-col half

    for (int i = tid; i < 4608; i += 256) {          // 2 ch x 192 rows x 12 int4
        int cc = i / 2304, j = i % 2304;
        int row = j / 12, v8 = j % 12;
        cp_async16(smaddr(wsc + cc * 19968 + row * 104 + v8 * 8),
                   g_wproj + row * 192 + cc * 96 + v8 * 8);
    }
    for (int i = tid; i < 1536; i += 256) {          // 64 rows x 24 int4
        int row = i / 24, v8 = i % 24;
        cp_async16(smaddr(abuf + row * 200 + v8 * 8),
                   g_o + (size_t)(rbase0 + row) * CDIM + v8 * 8);
    }
    cp_commit();
    cp_wait0();
    __syncthreads();

    __half* wc = wsc + ch * 19968;

    #pragma unroll
    for (int blk = 0; blk < 2; blk++) {
        unsigned A[12][4];
        {
            int r = mt * 16 + (lane & 7) + ((lane >> 3) & 1) * 8;
            #pragma unroll
            for (int kt = 0; kt < 12; kt++) {
                int c = kt * 16 + (lane >> 4) * 8;
                ldsm4(A[kt][0], A[kt][1], A[kt][2], A[kt][3],
                      smaddr(abuf + r * 200 + c));
            }
        }
        __syncthreads();

        if (blk == 0) {
            for (int i = tid; i < 1536; i += 256) {
                int row = i / 24, v8 = i % 24;
                cp_async16(smaddr(abuf + row * 200 + v8 * 8),
                           g_o + (size_t)(rbase0 + 64 + row) * CDIM + v8 * 8);
            }
            cp_commit();
        }

        float C[12][4];
        #pragma unroll
        for (int n = 0; n < 12; n++)
            #pragma unroll
            for (int e = 0; e < 4; e++) C[n][e] = 0.0f;

        #pragma unroll
        for (int kt = 0; kt < 12; kt++) {
            int rB = kt * 16 + (lane & 7) + ((lane >> 3) & 1) * 8;
            #pragma unroll
            for (int np = 0; np < 6; np++) {
                unsigned b0, b1, b2, b3;
                int cB = np * 16 + (lane >> 4) * 8;
                ldsm4t(b0, b1, b2, b3, smaddr(wc + rB * 104 + cB));
                mma16816(C[2 * np],     A[kt][0], A[kt][1], A[kt][2], A[kt][3], b0, b1);
                mma16816(C[2 * np + 1], A[kt][0], A[kt][1], A[kt][2], A[kt][3], b2, b3);
            }
        }

        {
            int orow = rbase0 + blk * 64 + mt * 16 + (lane >> 2);
            float* g0 = out + (size_t)orow * CDIM + ch * 96;
            float* g8 = g0 + (size_t)8 * CDIM;
            #pragma unroll
            for (int n = 0; n < 12; n++) {
                int col = 8 * n + c0;
                float2 bb = *(const float2*)(bproj + ch * 96 + col);
                *(float2*)(g0 + col) = make_float2(C[n][0] + bb.x, C[n][1] + bb.y);
                *(float2*)(g8 + col) = make_float2(C[n][2] + bb.x, C[n][3] + bb.y);
            }
        }

        if (blk == 0) {
            cp_wait0();
            __syncthreads();
        }
    }
}

extern "C" void kernel_launch(void* const* d_in, const int* in_sizes, int n_in,
                              void* d_out, int out_size)
{
    (void)in_sizes; (void)n_in; (void)out_size;
    const float* x    = (const float*)d_in[0];
    const int*   mask = (const int*)  d_in[1];
    const float* wq   = (const float*)d_in[2];
    const float* bq   = (const float*)d_in[3];
    const float* wpj  = (const float*)d_in[4];
    const float* bp   = (const float*)d_in[5];
    float* out = (float*)d_out;

    conv_w<<<(CDIM * 3 * CDIM + 255) / 256, 256>>>(wq, wpj);

    cudaFuncSetAttribute(qkv_gemm, cudaFuncAttributeMaxDynamicSharedMemorySize, K1_SMEM);
    qkv_gemm<<<QKV_ROWS / 128, 256, K1_SMEM>>>(x, bq);

    cudaFuncSetAttribute(attn_only, cudaFuncAttributeMaxDynamicSharedMemorySize, K2_SMEM);
    attn_only<<<B_TOT, 256, K2_SMEM>>>(mask);

    cudaFuncSetAttribute(proj_gemm, cudaFuncAttributeMaxDynamicSharedMemorySize, K3_SMEM);
    proj_gemm<<<QKV_ROWS / 128, 256, K3_SMEM>>>(bp, out);
}

// round 15
// speedup vs baseline: 1.3661x; 1.0447x over previous
#include <cstdint>
#include <stdint.h>
#include <cuda_runtime.h>
#include <cuda_fp16.h>

#define B_TOT   8192
#define NTOK    49
#define CDIM    192
#define NH      6
#define HDIM    32
#define SCALE_F 0.17677669529663687f   // 1/sqrt(32)
#define QKV_ROWS (B_TOT * NTOK)        // 401408

// fp16 copies of the weights (converted by conv_w each call; deterministic)
__device__ __align__(16) __half g_wqkv[CDIM * 3 * CDIM];   // [192][576] row-major
__device__ __align__(16) __half g_wproj[CDIM * CDIM];      // [192][192] row-major
// fp16 qkv scratch, HEAD-MAJOR: [sec(3)][head(6)][b*49+n][32]
__device__ __align__(16) __half g_qkv[QKV_ROWS * 3 * CDIM];
// fp16 attention-output scratch: [B_*N][192] row-major
__device__ __align__(16) __half g_o[QKV_ROWS * CDIM];

__global__ void conv_w(const float* __restrict__ wq, const float* __restrict__ wp) {
    int i = blockIdx.x * 256 + threadIdx.x;
    if (i < CDIM * 3 * CDIM) g_wqkv[i]  = __float2half_rn(wq[i]);
    if (i < CDIM * CDIM)     g_wproj[i] = __float2half_rn(wp[i]);
}

// ---------------------------------------------------------------------------
// raw-PTX helpers
// ---------------------------------------------------------------------------
__device__ __forceinline__ unsigned smaddr(const void* p) {
    return (unsigned)__cvta_generic_to_shared(p);
}
__device__ __forceinline__ void ldsm4(unsigned& r0, unsigned& r1, unsigned& r2, unsigned& r3,
                                      unsigned a) {
    asm volatile("ldmatrix.sync.aligned.m8n8.x4.shared.b16 {%0,%1,%2,%3}, [%4];"
                 : "=r"(r0), "=r"(r1), "=r"(r2), "=r"(r3) : "r"(a));
}
__device__ __forceinline__ void ldsm4t(unsigned& r0, unsigned& r1, unsigned& r2, unsigned& r3,
                                       unsigned a) {
    asm volatile("ldmatrix.sync.aligned.m8n8.x4.trans.shared.b16 {%0,%1,%2,%3}, [%4];"
                 : "=r"(r0), "=r"(r1), "=r"(r2), "=r"(r3) : "r"(a));
}
__device__ __forceinline__ void mma16816(float* c,
                                         unsigned a0, unsigned a1, unsigned a2, unsigned a3,
                                         unsigned b0, unsigned b1) {
    asm volatile(
        "mma.sync.aligned.m16n8k16.row.col.f32.f16.f16.f32 "
        "{%0,%1,%2,%3},{%4,%5,%6,%7},{%8,%9},{%0,%1,%2,%3};"
        : "+f"(c[0]), "+f"(c[1]), "+f"(c[2]), "+f"(c[3])
        : "r"(a0), "r"(a1), "r"(a2), "r"(a3), "r"(b0), "r"(b1));
}
__device__ __forceinline__ unsigned pack_h2(float a, float b) {
    __half2 h = __floats2half2_rn(a, b);
    return *(unsigned*)&h;
}
__device__ __forceinline__ void cp_async16(unsigned dst, const void* src) {
    asm volatile("cp.async.cg.shared.global [%0], [%1], 16;" :: "r"(dst), "l"(src));
}
__device__ __forceinline__ void cp_commit() {
    asm volatile("cp.async.commit_group;");
}
__device__ __forceinline__ void cp_wait0() {
    asm volatile("cp.async.wait_group 0;");
}

// ============================================================================
// Kernel 1: QKV projection GEMM, raw mma, double-buffered cp.async staging.
// Epilogue now writes HEAD-MAJOR g_qkv: [sec][head][row][32].
// ============================================================================
#define K1_SMEM 79872

__global__ void __launch_bounds__(256, 2)
qkv_gemm(const float* __restrict__ x, const float* __restrict__ bqkv)
{
    extern __shared__ __align__(128) char smem[];

    const int tid  = threadIdx.x;
    const int w    = tid >> 5;
    const int lane = tid & 31;
    const int rbase = blockIdx.x * 128 + w * 16;
    const int c0 = 2 * (lane & 3);

    {
        __half* wb = (__half*)smem;
        for (int i = tid; i < 2304; i += 256) {      // 192 rows * 12 int4
            int row = i / 12, v8 = i % 12;
            cp_async16(smaddr(wb + row * 104 + v8 * 8),
                       g_wqkv + row * 576 + v8 * 8);
        }
        cp_commit();
    }

    unsigned A[12][4];
    {
        const int r0 = rbase + (lane >> 2);
        const float* xr0 = x + (size_t)r0 * CDIM;
        const float* xr8 = xr0 + 8 * CDIM;
        #pragma unroll
        for (int kt = 0; kt < 12; kt++) {
            int c = kt * 16 + c0;
            float2 v;
            v = *(const float2*)(xr0 + c);     A[kt][0] = pack_h2(v.x, v.y);
            v = *(const float2*)(xr8 + c);     A[kt][1] = pack_h2(v.x, v.y);
            v = *(const float2*)(xr0 + c + 8); A[kt][2] = pack_h2(v.x, v.y);
            v = *(const float2*)(xr8 + c + 8); A[kt][3] = pack_h2(v.x, v.y);
        }
    }

    cp_wait0();
    __syncthreads();

    const int orow = rbase + (lane >> 2);

    for (int nc = 0; nc < 6; nc++) {
        __half* wsc = (__half*)(smem + (nc & 1) * 39936);

        if (nc < 5) {
            __half* wb = (__half*)(smem + ((nc + 1) & 1) * 39936);
            for (int i = tid; i < 2304; i += 256) {
                int row = i / 12, v8 = i % 12;
                cp_async16(smaddr(wb + row * 104 + v8 * 8),
                           g_wqkv + row * 576 + (nc + 1) * 96 + v8 * 8);
            }
            cp_commit();
        }

        float C[12][4];
        #pragma unroll
        for (int n = 0; n < 12; n++)
            #pragma unroll
            for (int e = 0; e < 4; e++) C[n][e] = 0.0f;

        #pragma unroll
        for (int kt = 0; kt < 12; kt++) {
            int rB = kt * 16 + (lane & 7) + ((lane >> 3) & 1) * 8;
            #pragma unroll
            for (int np = 0; np < 6; np++) {
                unsigned b0, b1, b2, b3;
                int cB = np * 16 + (lane >> 4) * 8;
                ldsm4t(b0, b1, b2, b3, smaddr(wsc + rB * 104 + cB));
                mma16816(C[2 * np],     A[kt][0], A[kt][1], A[kt][2], A[kt][3], b0, b1);
                mma16816(C[2 * np + 1], A[kt][0], A[kt][1], A[kt][2], A[kt][3], b2, b3);
            }
        }

        // ---- epilogue: +bias, fp16, head-major global store ----
        {
            const int sec   = nc >> 1;
            const int headb = (nc & 1) * 3;
            #pragma unroll
            for (int n = 0; n < 12; n++) {
                int head = headb + (n >> 2);
                int hd   = (n & 3) * 8 + c0;
                float2 bb = *(const float2*)(bqkv + nc * 96 + n * 8 + c0);
                __half* h0 = g_qkv +
                    ((size_t)(sec * 6 + head) * QKV_ROWS + orow) * 32 + hd;
                __half* h8 = h0 + (size_t)8 * 32;
                *(__half2*)h0 = __floats2half2_rn(C[n][0] + bb.x, C[n][1] + bb.y);
                *(__half2*)h8 = __floats2half2_rn(C[n][2] + bb.x, C[n][3] + bb.y);
            }
        }

        if (nc < 5) {
            cp_wait0();
            __syncthreads();
        }
    }
}

// ============================================================================
// Kernel 2: attention ONLY, one CTA per batch item.
// Head-pair double buffering with CONTIGUOUS cp.async (head-major g_qkv):
// pair hp+1 streams in while pair hp computes. Per-matrix smem stride 40
// halves (80B) -> conflict-free ldsm. smem: 2 bufs x 6 mats x 64 x 40 halves
// = 61440 B | mbs @61440 -> 61456 total; 3 CTAs/SM.
// ============================================================================
#define MATS  2560                     // halves per matrix buffer (64 x 40)
#define PAIRB (6 * MATS)               // halves per pair buffer
#define K2_SMEM 61456

__global__ void __launch_bounds__(256, 3)
attn_only(const int* __restrict__ mask)
{
    extern __shared__ __align__(128) char smem[];
    __half*   qbufs = (__half*)(smem);               // 2 x PAIRB halves
    unsigned* mbs   = (unsigned*)(smem + 61440);

    const int b    = blockIdx.x;
    const int tid  = threadIdx.x;
    const int w    = tid >> 5;
    const int lane = tid & 31;
    const int q2   = 2 * (lane & 3);

    // ---- mask ballot ----
    {
        int valid = 0;
        if (tid < 64) valid = (tid < NTOK) ? (mask[b * NTOK + tid] != 0) : 0;
        unsigned bal = __ballot_sync(0xffffffffu, valid);
        if (w < 2 && lane == 0) mbs[w] = bal;
    }
    // ---- zero pad rows 49..63 of every matrix, both buffers ----
    for (int i = tid; i < 2 * 6 * 15 * 5; i += 256) {   // 900 int4
        int buf = i / 450, j = i % 450;
        int mat = j / 75, k = j % 75;
        int r = 49 + k / 5, v4 = k % 5;
        *(int4*)(qbufs + buf * PAIRB + mat * MATS + r * 40 + v4 * 8) =
            make_int4(0, 0, 0, 0);
    }
    // ---- stage head pair 0 into buf 0 (contiguous blocks) ----
    for (int i = tid; i < 6 * NTOK * 4; i += 256) {     // 1176 int4
        int blk = i / (NTOK * 4), j = i % (NTOK * 4);
        int row = j / 4, v4 = j % 4;
        int hx = blk / 3, sec = blk % 3;
        cp_async16(smaddr(qbufs + (hx * 3 + sec) * MATS + row * 40 + v4 * 8),
                   g_qkv + ((size_t)(sec * 6 + hx) * QKV_ROWS + (size_t)b * NTOK + row) * 32 + v4 * 8);
    }
    cp_commit();

    const int hh = w >> 2;                 // head within pair
    const int m  = w & 3;                  // m-tile (16 q rows)

    for (int hp = 0; hp < 3; hp++) {
        cp_wait0();
        __syncthreads();   // buffer hp ready; compute hp-1 done (WAR for hp+1's buffer)
        const unsigned mb0 = mbs[0], mb1 = mbs[1];

        // ---- prefetch head pair hp+1 into the other buffer ----
        if (hp < 2) {
            __half* wb = qbufs + ((hp + 1) & 1) * PAIRB;
            for (int i = tid; i < 6 * NTOK * 4; i += 256) {
                int blk = i / (NTOK * 4), j = i % (NTOK * 4);
                int row = j / 4, v4 = j % 4;
                int hx = blk / 3, sec = blk % 3;
                int h = (hp + 1) * 2 + hx;
                cp_async16(smaddr(wb + (hx * 3 + sec) * MATS + row * 40 + v4 * 8),
                           g_qkv + ((size_t)(sec * 6 + h) * QKV_ROWS + (size_t)b * NTOK + row) * 32 + v4 * 8);
            }
            cp_commit();
        }

        __half* qsq = qbufs + (hp & 1) * PAIRB + (hh * 3 + 0) * MATS;
        __half* qsk = qbufs + (hp & 1) * PAIRB + (hh * 3 + 1) * MATS;
        __half* qsv = qbufs + (hp & 1) * PAIRB + (hh * 3 + 2) * MATS;

        // ---- GEMM2 in registers: S[16][64] = Q_tile @ K^T ----
        float s[32];
        #pragma unroll
        for (int i = 0; i < 32; i++) s[i] = 0.0f;

        #pragma unroll
        for (int kt = 0; kt < 2; kt++) {
            unsigned a0, a1, a2, a3;
            {
                int r = m * 16 + (lane & 7) + ((lane >> 3) & 1) * 8;
                int c = kt * 16 + (lane >> 4) * 8;
                ldsm4(a0, a1, a2, a3, smaddr(qsq + r * 40 + c));
            }
            #pragma unroll
            for (int ng = 0; ng < 4; ng++) {
                unsigned b0, b1, b2, b3;
                int r = ng * 16 + (lane & 7) + (lane >> 4) * 8;
                int c = kt * 16 + ((lane >> 3) & 1) * 8;
                ldsm4(b0, b1, b2, b3, smaddr(qsk + r * 40 + c));
                mma16816(s + (2 * ng) * 4,     a0, a1, a2, a3, b0, b1);
                mma16816(s + (2 * ng + 1) * 4, a0, a1, a2, a3, b2, b3);
            }
        }

        // ---- masked softmax in registers ----
        float mxA = -1e30f, mxB = -1e30f;
        #pragma unroll
        for (int t = 0; t < 8; t++) {
            int c0 = 8 * t + q2;
            unsigned vm = (c0 < 32) ? (mb0 >> c0) : (mb1 >> (c0 - 32));
            s[4 * t + 0] = (vm & 1) ? s[4 * t + 0] * SCALE_F : -1e30f;
            s[4 * t + 1] = (vm & 2) ? s[4 * t + 1] * SCALE_F : -1e30f;
            s[4 * t + 2] = (vm & 1) ? s[4 * t + 2] * SCALE_F : -1e30f;
            s[4 * t + 3] = (vm & 2) ? s[4 * t + 3] * SCALE_F : -1e30f;
            mxA = fmaxf(mxA, fmaxf(s[4 * t + 0], s[4 * t + 1]));
            mxB = fmaxf(mxB, fmaxf(s[4 * t + 2], s[4 * t + 3]));
        }
        mxA = fmaxf(mxA, __shfl_xor_sync(0xffffffffu, mxA, 1));
        mxA = fmaxf(mxA, __shfl_xor_sync(0xffffffffu, mxA, 2));
        mxB = fmaxf(mxB, __shfl_xor_sync(0xffffffffu, mxB, 1));
        mxB = fmaxf(mxB, __shfl_xor_sync(0xffffffffu, mxB, 2));

        float smA = 0.0f, smB = 0.0f;
        #pragma unroll
        for (int t = 0; t < 8; t++) {
            s[4 * t + 0] = __expf(s[4 * t + 0] - mxA);
            s[4 * t + 1] = __expf(s[4 * t + 1] - mxA);
            s[4 * t + 2] = __expf(s[4 * t + 2] - mxB);
            s[4 * t + 3] = __expf(s[4 * t + 3] - mxB);
            smA += s[4 * t + 0] + s[4 * t + 1];
            smB += s[4 * t + 2] + s[4 * t + 3];
        }
        smA += __shfl_xor_sync(0xffffffffu, smA, 1);
        smA += __shfl_xor_sync(0xffffffffu, smA, 2);
        smB += __shfl_xor_sync(0xffffffffu, smB, 1);
        smB += __shfl_xor_sync(0xffffffffu, smB, 2);
        const float invA = 1.0f / smA, invB = 1.0f / smB;

        // ---- P accumulator -> A-fragments ----
        unsigned pa[16];
        #pragma unroll
        for (int kc = 0; kc < 4; kc++) {
            float* t0 = s + (2 * kc) * 4;
            float* t1 = s + (2 * kc + 1) * 4;
            pa[4 * kc + 0] = pack_h2(t0[0] * invA, t0[1] * invA);
            pa[4 * kc + 1] = pack_h2(t0[2] * invB, t0[3] * invB);
            pa[4 * kc + 2] = pack_h2(t1[0] * invA, t1[1] * invA);
            pa[4 * kc + 3] = pack_h2(t1[2] * invB, t1[3] * invB);
        }

        // ---- GEMM3: O[16][32] = P @ V ----
        float o[16];
        #pragma unroll
        for (int i = 0; i < 16; i++) o[i] = 0.0f;
        #pragma unroll
        for (int kc = 0; kc < 4; kc++) {
            #pragma unroll
            for (int nh = 0; nh < 2; nh++) {
                unsigned b0, b1, b2, b3;
                int r = kc * 16 + (lane & 7) + ((lane >> 3) & 1) * 8;
                int c = nh * 16 + (lane >> 4) * 8;
                ldsm4t(b0, b1, b2, b3, smaddr(qsv + r * 40 + c));
                mma16816(o + (2 * nh) * 4,
                         pa[4 * kc + 0], pa[4 * kc + 1], pa[4 * kc + 2], pa[4 * kc + 3],
                         b0, b1);
                mma16816(o + (2 * nh + 1) * 4,
                         pa[4 * kc + 0], pa[4 * kc + 1], pa[4 * kc + 2], pa[4 * kc + 3],
                         b2, b3);
            }
        }

        // ---- store O tile directly to g_o scratch (fp16) ----
        {
            int h  = hp * 2 + hh;
            int rA = m * 16 + (lane >> 2);
            __half* r0p = g_o + ((size_t)b * NTOK + rA) * CDIM + h * HDIM;
            __half* r8p = r0p + (size_t)8 * CDIM;
            #pragma unroll
            for (int t = 0; t < 4; t++) {
                int col = 8 * t + q2;
                if (rA < NTOK)
                    *(__half2*)(r0p + col) = __floats2half2_rn(o[4 * t + 0], o[4 * t + 1]);
                if (rA + 8 < NTOK)
                    *(__half2*)(r8p + col) = __floats2half2_rn(o[4 * t + 2], o[4 * t + 3]);
            }
        }
    }
}

// ============================================================================
// Kernel 3: output projection GEMM (unchanged).
// ============================================================================
#define K3_SMEM 105472

__global__ void __launch_bounds__(256, 2)
proj_gemm(const float* __restrict__ bproj, float* __restrict__ out)
{
    extern __shared__ __align__(128) char smem[];
    __half* wsc  = (__half*)smem;                   // 2 chunks, stride 19968 halves
    __half* abuf = (__half*)(smem + 79872);         // [64][200] halves

    const int tid  = threadIdx.x;
    const int w    = tid >> 5;
    const int lane = tid & 31;
    const int rbase0 = blockIdx.x * 128;
    const int c0 = 2 * (lane & 3);
    const int mt = w & 3;                            // m-tile within 64-row sub-block
    const int ch = w >> 2;                           // 96-col half

    for (int i = tid; i < 4608; i += 256) {          // 2 ch x 192 rows x 12 int4
        int cc = i / 2304, j = i % 2304;
        int row = j / 12, v8 = j % 12;
        cp_async16(smaddr(wsc + cc * 19968 + row * 104 + v8 * 8),
                   g_wproj + row * 192 + cc * 96 + v8 * 8);
    }
    for (int i = tid; i < 1536; i += 256) {          // 64 rows x 24 int4
        int row = i / 24, v8 = i % 24;
        cp_async16(smaddr(abuf + row * 200 + v8 * 8),
                   g_o + (size_t)(rbase0 + row) * CDIM + v8 * 8);
    }
    cp_commit();
    cp_wait0();
    __syncthreads();

    __half* wc = wsc + ch * 19968;

    #pragma unroll
    for (int blk = 0; blk < 2; blk++) {
        unsigned A[12][4];
        {
            int r = mt * 16 + (lane & 7) + ((lane >> 3) & 1) * 8;
            #pragma unroll
            for (int kt = 0; kt < 12; kt++) {
                int c = kt * 16 + (lane >> 4) * 8;
                ldsm4(A[kt][0], A[kt][1], A[kt][2], A[kt][3],
                      smaddr(abuf + r * 200 + c));
            }
        }
        __syncthreads();

        if (blk == 0) {
            for (int i = tid; i < 1536; i += 256) {
                int row = i / 24, v8 = i % 24;
                cp_async16(smaddr(abuf + row * 200 + v8 * 8),
                           g_o + (size_t)(rbase0 + 64 + row) * CDIM + v8 * 8);
            }
            cp_commit();
        }

        float C[12][4];
        #pragma unroll
        for (int n = 0; n < 12; n++)
            #pragma unroll
            for (int e = 0; e < 4; e++) C[n][e] = 0.0f;

        #pragma unroll
        for (int kt = 0; kt < 12; kt++) {
            int rB = kt * 16 + (lane & 7) + ((lane >> 3) & 1) * 8;
            #pragma unroll
            for (int np = 0; np < 6; np++) {
                unsigned b0, b1, b2, b3;
                int cB = np * 16 + (lane >> 4) * 8;
                ldsm4t(b0, b1, b2, b3, smaddr(wc + rB * 104 + cB));
                mma16816(C[2 * np],     A[kt][0], A[kt][1], A[kt][2], A[kt][3], b0, b1);
                mma16816(C[2 * np + 1], A[kt][0], A[kt][1], A[kt][2], A[kt][3], b2, b3);
            }
        }

        {
            int orow = rbase0 + blk * 64 + mt * 16 + (lane >> 2);
            float* g0 = out + (size_t)orow * CDIM + ch * 96;
            float* g8 = g0 + (size_t)8 * CDIM;
            #pragma unroll
            for (int n = 0; n < 12; n++) {
                int col = 8 * n + c0;
                float2 bb = *(const float2*)(bproj + ch * 96 + col);
                *(float2*)(g0 + col) = make_float2(C[n][0] + bb.x, C[n][1] + bb.y);
                *(float2*)(g8 + col) = make_float2(C[n][2] + bb.x, C[n][3] + bb.y);
            }
        }

        if (blk == 0) {
            cp_wait0();
            __syncthreads();
        }
    }
}

extern "C" void kernel_launch(void* const* d_in, const int* in_sizes, int n_in,
                              void* d_out, int out_size)
{
    (void)in_sizes; (void)n_in; (void)out_size;
    const float* x    = (const float*)d_in[0];
    const int*   mask = (const int*)  d_in[1];
    const float* wq   = (const float*)d_in[2];
    const float* bq   = (const float*)d_in[3];
    const float* wpj  = (const float*)d_in[4];
    const float* bp   = (const float*)d_in[5];
    float* out = (float*)d_out;

    conv_w<<<(CDIM * 3 * CDIM + 255) / 256, 256>>>(wq, wpj);

    cudaFuncSetAttribute(qkv_gemm, cudaFuncAttributeMaxDynamicSharedMemorySize, K1_SMEM);
    qkv_gemm<<<QKV_ROWS / 128, 256, K1_SMEM>>>(x, bq);

    cudaFuncSetAttribute(attn_only, cudaFuncAttributeMaxDynamicSharedMemorySize, K2_SMEM);
    attn_only<<<B_TOT, 256, K2_SMEM>>>(mask);

    cudaFuncSetAttribute(proj_gemm, cudaFuncAttributeMaxDynamicSharedMemorySize, K3_SMEM);
    proj_gemm<<<QKV_ROWS / 128, 256, K3_SMEM>>>(bp, out);
}

// round 16
// speedup vs baseline: 1.3961x; 1.0219x over previous
#include <cstdint>
#include <stdint.h>
#include <cuda_runtime.h>
#include <cuda_fp16.h>

#define B_TOT   8192
#define NTOK    49
#define CDIM    192
#define NH      6
#define HDIM    32
#define SCALE_F 0.17677669529663687f   // 1/sqrt(32)
#define QKV_ROWS (B_TOT * NTOK)        // 401408

// fp16 copies of the weights (converted by conv_w each call; deterministic)
__device__ __align__(16) __half g_wqkv[CDIM * 3 * CDIM];   // [192][576] row-major
__device__ __align__(16) __half g_wproj[CDIM * CDIM];      // [192][192] row-major
// fp16 qkv scratch, HEAD-MAJOR: [sec(3)][head(6)][b*49+n][32]
__device__ __align__(16) __half g_qkv[QKV_ROWS * 3 * CDIM];
// fp16 attention-output scratch: [B_*N][192] row-major
__device__ __align__(16) __half g_o[QKV_ROWS * CDIM];

__global__ void conv_w(const float* __restrict__ wq, const float* __restrict__ wp) {
    int i = blockIdx.x * 256 + threadIdx.x;
    if (i < CDIM * 3 * CDIM) g_wqkv[i]  = __float2half_rn(wq[i]);
    if (i < CDIM * CDIM)     g_wproj[i] = __float2half_rn(wp[i]);
}

// ---------------------------------------------------------------------------
// raw-PTX helpers
// ---------------------------------------------------------------------------
__device__ __forceinline__ unsigned smaddr(const void* p) {
    return (unsigned)__cvta_generic_to_shared(p);
}
__device__ __forceinline__ void ldsm4(unsigned& r0, unsigned& r1, unsigned& r2, unsigned& r3,
                                      unsigned a) {
    asm volatile("ldmatrix.sync.aligned.m8n8.x4.shared.b16 {%0,%1,%2,%3}, [%4];"
                 : "=r"(r0), "=r"(r1), "=r"(r2), "=r"(r3) : "r"(a));
}
__device__ __forceinline__ void ldsm4t(unsigned& r0, unsigned& r1, unsigned& r2, unsigned& r3,
                                       unsigned a) {
    asm volatile("ldmatrix.sync.aligned.m8n8.x4.trans.shared.b16 {%0,%1,%2,%3}, [%4];"
                 : "=r"(r0), "=r"(r1), "=r"(r2), "=r"(r3) : "r"(a));
}
__device__ __forceinline__ void mma16816(float* c,
                                         unsigned a0, unsigned a1, unsigned a2, unsigned a3,
                                         unsigned b0, unsigned b1) {
    asm volatile(
        "mma.sync.aligned.m16n8k16.row.col.f32.f16.f16.f32 "
        "{%0,%1,%2,%3},{%4,%5,%6,%7},{%8,%9},{%0,%1,%2,%3};"
        : "+f"(c[0]), "+f"(c[1]), "+f"(c[2]), "+f"(c[3])
        : "r"(a0), "r"(a1), "r"(a2), "r"(a3), "r"(b0), "r"(b1));
}
__device__ __forceinline__ unsigned pack_h2(float a, float b) {
    __half2 h = __floats2half2_rn(a, b);
    return *(unsigned*)&h;
}
__device__ __forceinline__ void cp_async16(unsigned dst, const void* src) {
    asm volatile("cp.async.cg.shared.global [%0], [%1], 16;" :: "r"(dst), "l"(src));
}
__device__ __forceinline__ void cp_commit() {
    asm volatile("cp.async.commit_group;");
}
__device__ __forceinline__ void cp_wait0() {
    asm volatile("cp.async.wait_group 0;");
}

// ============================================================================
// Kernel 1: QKV projection GEMM, raw mma, double-buffered cp.async staging.
// Epilogue writes HEAD-MAJOR g_qkv: [sec][head][row][32]. (unchanged)
// ============================================================================
#define K1_SMEM 79872

__global__ void __launch_bounds__(256, 2)
qkv_gemm(const float* __restrict__ x, const float* __restrict__ bqkv)
{
    extern __shared__ __align__(128) char smem[];

    const int tid  = threadIdx.x;
    const int w    = tid >> 5;
    const int lane = tid & 31;
    const int rbase = blockIdx.x * 128 + w * 16;
    const int c0 = 2 * (lane & 3);

    {
        __half* wb = (__half*)smem;
        for (int i = tid; i < 2304; i += 256) {      // 192 rows * 12 int4
            int row = i / 12, v8 = i % 12;
            cp_async16(smaddr(wb + row * 104 + v8 * 8),
                       g_wqkv + row * 576 + v8 * 8);
        }
        cp_commit();
    }

    unsigned A[12][4];
    {
        const int r0 = rbase + (lane >> 2);
        const float* xr0 = x + (size_t)r0 * CDIM;
        const float* xr8 = xr0 + 8 * CDIM;
        #pragma unroll
        for (int kt = 0; kt < 12; kt++) {
            int c = kt * 16 + c0;
            float2 v;
            v = *(const float2*)(xr0 + c);     A[kt][0] = pack_h2(v.x, v.y);
            v = *(const float2*)(xr8 + c);     A[kt][1] = pack_h2(v.x, v.y);
            v = *(const float2*)(xr0 + c + 8); A[kt][2] = pack_h2(v.x, v.y);
            v = *(const float2*)(xr8 + c + 8); A[kt][3] = pack_h2(v.x, v.y);
        }
    }

    cp_wait0();
    __syncthreads();

    const int orow = rbase + (lane >> 2);

    for (int nc = 0; nc < 6; nc++) {
        __half* wsc = (__half*)(smem + (nc & 1) * 39936);

        if (nc < 5) {
            __half* wb = (__half*)(smem + ((nc + 1) & 1) * 39936);
            for (int i = tid; i < 2304; i += 256) {
                int row = i / 12, v8 = i % 12;
                cp_async16(smaddr(wb + row * 104 + v8 * 8),
                           g_wqkv + row * 576 + (nc + 1) * 96 + v8 * 8);
            }
            cp_commit();
        }

        float C[12][4];
        #pragma unroll
        for (int n = 0; n < 12; n++)
            #pragma unroll
            for (int e = 0; e < 4; e++) C[n][e] = 0.0f;

        #pragma unroll
        for (int kt = 0; kt < 12; kt++) {
            int rB = kt * 16 + (lane & 7) + ((lane >> 3) & 1) * 8;
            #pragma unroll
            for (int np = 0; np < 6; np++) {
                unsigned b0, b1, b2, b3;
                int cB = np * 16 + (lane >> 4) * 8;
                ldsm4t(b0, b1, b2, b3, smaddr(wsc + rB * 104 + cB));
                mma16816(C[2 * np],     A[kt][0], A[kt][1], A[kt][2], A[kt][3], b0, b1);
                mma16816(C[2 * np + 1], A[kt][0], A[kt][1], A[kt][2], A[kt][3], b2, b3);
            }
        }

        // ---- epilogue: +bias, fp16, head-major global store ----
        {
            const int sec   = nc >> 1;
            const int headb = (nc & 1) * 3;
            #pragma unroll
            for (int n = 0; n < 12; n++) {
                int head = headb + (n >> 2);
                int hd   = (n & 3) * 8 + c0;
                float2 bb = *(const float2*)(bqkv + nc * 96 + n * 8 + c0);
                __half* h0 = g_qkv +
                    ((size_t)(sec * 6 + head) * QKV_ROWS + orow) * 32 + hd;
                __half* h8 = h0 + (size_t)8 * 32;
                *(__half2*)h0 = __floats2half2_rn(C[n][0] + bb.x, C[n][1] + bb.y);
                *(__half2*)h8 = __floats2half2_rn(C[n][2] + bb.x, C[n][3] + bb.y);
            }
        }

        if (nc < 5) {
            cp_wait0();
            __syncthreads();
        }
    }
}

// ============================================================================
// Kernel 2: attention ONLY, TWO batch items per CTA (grid 4096).
// 6 pipelined phases (batch-major: b0 pairs 0-2, then b0+1 pairs 0-2) with
// head-pair double buffering + contiguous cp.async. QK skips the always-
// padding n-tile (cols 56-63). smem: 2 bufs x 6 mats x 64 x 40 halves
// = 61440 B | mbs u32[4] @61440 -> 61456; 3 CTAs/SM.
// ============================================================================
#define MATS  2560                     // halves per matrix buffer (64 x 40)
#define PAIRB (6 * MATS)               // halves per pair buffer
#define K2_SMEM 61456

__global__ void __launch_bounds__(256, 3)
attn_only(const int* __restrict__ mask)
{
    extern __shared__ __align__(128) char smem[];
    __half*   qbufs = (__half*)(smem);               // 2 x PAIRB halves
    unsigned* mbs   = (unsigned*)(smem + 61440);     // 2 batches x 2 words

    const int b0   = blockIdx.x * 2;
    const int tid  = threadIdx.x;
    const int w    = tid >> 5;
    const int lane = tid & 31;
    const int q2   = 2 * (lane & 3);

    // ---- mask ballots for both batches ----
    {
        int valid = 0;
        if (tid < 128) {
            int bb = tid >> 6;                       // 0 or 1
            int tok = tid & 63;
            valid = (tok < NTOK) ? (mask[(b0 + bb) * NTOK + tok] != 0) : 0;
        }
        unsigned bal = __ballot_sync(0xffffffffu, valid);
        if (w < 4 && lane == 0) mbs[w] = bal;
    }
    // ---- zero pad rows 49..63 of every matrix, both buffers ----
    for (int i = tid; i < 2 * 6 * 15 * 5; i += 256) {   // 900 int4
        int buf = i / 450, j = i % 450;
        int mat = j / 75, k = j % 75;
        int r = 49 + k / 5, v4 = k % 5;
        *(int4*)(qbufs + buf * PAIRB + mat * MATS + r * 40 + v4 * 8) =
            make_int4(0, 0, 0, 0);
    }
    // ---- stage phase 0 (batch b0, pair 0) into buf 0 ----
    for (int i = tid; i < 6 * NTOK * 4; i += 256) {     // 1176 int4
        int blk = i / (NTOK * 4), j = i % (NTOK * 4);
        int row = j / 4, v4 = j % 4;
        int hx = blk / 3, sec = blk % 3;
        cp_async16(smaddr(qbufs + (hx * 3 + sec) * MATS + row * 40 + v4 * 8),
                   g_qkv + ((size_t)(sec * 6 + hx) * QKV_ROWS + (size_t)b0 * NTOK + row) * 32 + v4 * 8);
    }
    cp_commit();

    const int hh = w >> 2;                 // head within pair
    const int m  = w & 3;                  // m-tile (16 q rows)

    for (int ph = 0; ph < 6; ph++) {
        cp_wait0();
        __syncthreads();   // buffer ph ready; compute ph-1 done (WAR for ph+1's buffer)

        const int bsel = ph / 3;           // which batch this phase computes
        const int hp   = ph - bsel * 3;    // head pair within batch
        const unsigned mb0 = mbs[2 * bsel], mb1 = mbs[2 * bsel + 1];

        // ---- prefetch phase ph+1 into the other buffer ----
        if (ph < 5) {
            const int nbsel = (ph + 1) / 3;
            const int nhp   = (ph + 1) - nbsel * 3;
            const size_t nb = (size_t)(b0 + nbsel) * NTOK;
            __half* wb = qbufs + ((ph + 1) & 1) * PAIRB;
            for (int i = tid; i < 6 * NTOK * 4; i += 256) {
                int blk = i / (NTOK * 4), j = i % (NTOK * 4);
                int row = j / 4, v4 = j % 4;
                int hx = blk / 3, sec = blk % 3;
                int h = nhp * 2 + hx;
                cp_async16(smaddr(wb + (hx * 3 + sec) * MATS + row * 40 + v4 * 8),
                           g_qkv + ((size_t)(sec * 6 + h) * QKV_ROWS + nb + row) * 32 + v4 * 8);
            }
            cp_commit();
        }

        __half* qsq = qbufs + (ph & 1) * PAIRB + (hh * 3 + 0) * MATS;
        __half* qsk = qbufs + (ph & 1) * PAIRB + (hh * 3 + 1) * MATS;
        __half* qsv = qbufs + (ph & 1) * PAIRB + (hh * 3 + 2) * MATS;

        // ---- GEMM2 in registers: S[16][64] = Q_tile @ K^T ----
        // cols 56-63 are ALWAYS padding (NTOK=49): skip their mma, seed -1e30.
        float s[32];
        #pragma unroll
        for (int i = 0; i < 28; i++) s[i] = 0.0f;
        #pragma unroll
        for (int i = 28; i < 32; i++) s[i] = -1e30f;

        #pragma unroll
        for (int kt = 0; kt < 2; kt++) {
            unsigned a0, a1, a2, a3;
            {
                int r = m * 16 + (lane & 7) + ((lane >> 3) & 1) * 8;
                int c = kt * 16 + (lane >> 4) * 8;
                ldsm4(a0, a1, a2, a3, smaddr(qsq + r * 40 + c));
            }
            #pragma unroll
            for (int ng = 0; ng < 4; ng++) {
                unsigned b0r, b1r, b2r, b3r;
                int r = ng * 16 + (lane & 7) + (lane >> 4) * 8;
                int c = kt * 16 + ((lane >> 3) & 1) * 8;
                ldsm4(b0r, b1r, b2r, b3r, smaddr(qsk + r * 40 + c));
                mma16816(s + (2 * ng) * 4, a0, a1, a2, a3, b0r, b1r);
                if (ng < 3)
                    mma16816(s + (2 * ng + 1) * 4, a0, a1, a2, a3, b2r, b3r);
            }
        }

        // ---- masked softmax in registers ----
        float mxA = -1e30f, mxB = -1e30f;
        #pragma unroll
        for (int t = 0; t < 7; t++) {
            int c0 = 8 * t + q2;
            unsigned vm = (c0 < 32) ? (mb0 >> c0) : (mb1 >> (c0 - 32));
            s[4 * t + 0] = (vm & 1) ? s[4 * t + 0] * SCALE_F : -1e30f;
            s[4 * t + 1] = (vm & 2) ? s[4 * t + 1] * SCALE_F : -1e30f;
            s[4 * t + 2] = (vm & 1) ? s[4 * t + 2] * SCALE_F : -1e30f;
            s[4 * t + 3] = (vm & 2) ? s[4 * t + 3] * SCALE_F : -1e30f;
            mxA = fmaxf(mxA, fmaxf(s[4 * t + 0], s[4 * t + 1]));
            mxB = fmaxf(mxB, fmaxf(s[4 * t + 2], s[4 * t + 3]));
        }
        mxA = fmaxf(mxA, __shfl_xor_sync(0xffffffffu, mxA, 1));
        mxA = fmaxf(mxA, __shfl_xor_sync(0xffffffffu, mxA, 2));
        mxB = fmaxf(mxB, __shfl_xor_sync(0xffffffffu, mxB, 1));
        mxB = fmaxf(mxB, __shfl_xor_sync(0xffffffffu, mxB, 2));

        float smA = 0.0f, smB = 0.0f;
        #pragma unroll
        for (int t = 0; t < 8; t++) {
            s[4 * t + 0] = __expf(s[4 * t + 0] - mxA);
            s[4 * t + 1] = __expf(s[4 * t + 1] - mxA);
            s[4 * t + 2] = __expf(s[4 * t + 2] - mxB);
            s[4 * t + 3] = __expf(s[4 * t + 3] - mxB);
            smA += s[4 * t + 0] + s[4 * t + 1];
            smB += s[4 * t + 2] + s[4 * t + 3];
        }
        smA += __shfl_xor_sync(0xffffffffu, smA, 1);
        smA += __shfl_xor_sync(0xffffffffu, smA, 2);
        smB += __shfl_xor_sync(0xffffffffu, smB, 1);
        smB += __shfl_xor_sync(0xffffffffu, smB, 2);
        const float invA = 1.0f / smA, invB = 1.0f / smB;

        // ---- P accumulator -> A-fragments ----
        unsigned pa[16];
        #pragma unroll
        for (int kc = 0; kc < 4; kc++) {
            float* t0 = s + (2 * kc) * 4;
            float* t1 = s + (2 * kc + 1) * 4;
            pa[4 * kc + 0] = pack_h2(t0[0] * invA, t0[1] * invA);
            pa[4 * kc + 1] = pack_h2(t0[2] * invB, t0[3] * invB);
            pa[4 * kc + 2] = pack_h2(t1[0] * invA, t1[1] * invA);
            pa[4 * kc + 3] = pack_h2(t1[2] * invB, t1[3] * invB);
        }

        // ---- GEMM3: O[16][32] = P @ V ----
        float o[16];
        #pragma unroll
        for (int i = 0; i < 16; i++) o[i] = 0.0f;
        #pragma unroll
        for (int kc = 0; kc < 4; kc++) {
            #pragma unroll
            for (int nh = 0; nh < 2; nh++) {
                unsigned b0r, b1r, b2r, b3r;
                int r = kc * 16 + (lane & 7) + ((lane >> 3) & 1) * 8;
                int c = nh * 16 + (lane >> 4) * 8;
                ldsm4t(b0r, b1r, b2r, b3r, smaddr(qsv + r * 40 + c));
                mma16816(o + (2 * nh) * 4,
                         pa[4 * kc + 0], pa[4 * kc + 1], pa[4 * kc + 2], pa[4 * kc + 3],
                         b0r, b1r);
                mma16816(o + (2 * nh + 1) * 4,
                         pa[4 * kc + 0], pa[4 * kc + 1], pa[4 * kc + 2], pa[4 * kc + 3],
                         b2r, b3r);
            }
        }

        // ---- store O tile directly to g_o scratch (fp16) ----
        {
            int h  = hp * 2 + hh;
            int rA = m * 16 + (lane >> 2);
            __half* r0p = g_o + ((size_t)(b0 + bsel) * NTOK + rA) * CDIM + h * HDIM;
            __half* r8p = r0p + (size_t)8 * CDIM;
            #pragma unroll
            for (int t = 0; t < 4; t++) {
                int col = 8 * t + q2;
                if (rA < NTOK)
                    *(__half2*)(r0p + col) = __floats2half2_rn(o[4 * t + 0], o[4 * t + 1]);
                if (rA + 8 < NTOK)
                    *(__half2*)(r8p + col) = __floats2half2_rn(o[4 * t + 2], o[4 * t + 3]);
            }
        }
    }
}

// ============================================================================
// Kernel 3: output projection GEMM (unchanged).
// ============================================================================
#define K3_SMEM 105472

__global__ void __launch_bounds__(256, 2)
proj_gemm(const float* __restrict__ bproj, float* __restrict__ out)
{
    extern __shared__ __align__(128) char smem[];
    __half* wsc  = (__half*)smem;                   // 2 chunks, stride 19968 halves
    __half* abuf = (__half*)(smem + 79872);         // [64][200] halves

    const int tid  = threadIdx.x;
    const int w    = tid >> 5;
    const int lane = tid & 31;
    const int rbase0 = blockIdx.x * 128;
    const int c0 = 2 * (lane & 3);
    const int mt = w & 3;                            // m-tile within 64-row sub-block
    const int ch = w >> 2;                           // 96-col half

    for (int i = tid; i < 4608; i += 256) {          // 2 ch x 192 rows x 12 int4
        int cc = i / 2304, j = i % 2304;
        int row = j / 12, v8 = j % 12;
        cp_async16(smaddr(wsc + cc * 19968 + row * 104 + v8 * 8),
                   g_wproj + row * 192 + cc * 96 + v8 * 8);
    }
    for (int i = tid; i < 1536; i += 256) {          // 64 rows x 24 int4
        int row = i / 24, v8 = i % 24;
        cp_async16(smaddr(abuf + row * 200 + v8 * 8),
                   g_o + (size_t)(rbase0 + row) * CDIM + v8 * 8);
    }
    cp_commit();
    cp_wait0();
    __syncthreads();

    __half* wc = wsc + ch * 19968;

    #pragma unroll
    for (int blk = 0; blk < 2; blk++) {
        unsigned A[12][4];
        {
            int r = mt * 16 + (lane & 7) + ((lane >> 3) & 1) * 8;
            #pragma unroll
            for (int kt = 0; kt < 12; kt++) {
                int c = kt * 16 + (lane >> 4) * 8;
                ldsm4(A[kt][0], A[kt][1], A[kt][2], A[kt][3],
                      smaddr(abuf + r * 200 + c));
            }
        }
        __syncthreads();

        if (blk == 0) {
            for (int i = tid; i < 1536; i += 256) {
                int row = i / 24, v8 = i % 24;
                cp_async16(smaddr(abuf + row * 200 + v8 * 8),
                           g_o + (size_t)(rbase0 + 64 + row) * CDIM + v8 * 8);
            }
            cp_commit();
        }

        float C[12][4];
        #pragma unroll
        for (int n = 0; n < 12; n++)
            #pragma unroll
            for (int e = 0; e < 4; e++) C[n][e] = 0.0f;

        #pragma unroll
        for (int kt = 0; kt < 12; kt++) {
            int rB = kt * 16 + (lane & 7) + ((lane >> 3) & 1) * 8;
            #pragma unroll
            for (int np = 0; np < 6; np++) {
                unsigned b0, b1, b2, b3;
                int cB = np * 16 + (lane >> 4) * 8;
                ldsm4t(b0, b1, b2, b3, smaddr(wc + rB * 104 + cB));
                mma16816(C[2 * np],     A[kt][0], A[kt][1], A[kt][2], A[kt][3], b0, b1);
                mma16816(C[2 * np + 1], A[kt][0], A[kt][1], A[kt][2], A[kt][3], b2, b3);
            }
        }

        {
            int orow = rbase0 + blk * 64 + mt * 16 + (lane >> 2);
            float* g0 = out + (size_t)orow * CDIM + ch * 96;
            float* g8 = g0 + (size_t)8 * CDIM;
            #pragma unroll
            for (int n = 0; n < 12; n++) {
                int col = 8 * n + c0;
                float2 bb = *(const float2*)(bproj + ch * 96 + col);
                *(float2*)(g0 + col) = make_float2(C[n][0] + bb.x, C[n][1] + bb.y);
                *(float2*)(g8 + col) = make_float2(C[n][2] + bb.x, C[n][3] + bb.y);
            }
        }

        if (blk == 0) {
            cp_wait0();
            __syncthreads();
        }
    }
}

extern "C" void kernel_launch(void* const* d_in, const int* in_sizes, int n_in,
                              void* d_out, int out_size)
{
    (void)in_sizes; (void)n_in; (void)out_size;
    const float* x    = (const float*)d_in[0];
    const int*   mask = (const int*)  d_in[1];
    const float* wq   = (const float*)d_in[2];
    const float* bq   = (const float*)d_in[3];
    const float* wpj  = (const float*)d_in[4];
    const float* bp   = (const float*)d_in[5];
    float* out = (float*)d_out;

    conv_w<<<(CDIM * 3 * CDIM + 255) / 256, 256>>>(wq, wpj);

    cudaFuncSetAttribute(qkv_gemm, cudaFuncAttributeMaxDynamicSharedMemorySize, K1_SMEM);
    qkv_gemm<<<QKV_ROWS / 128, 256, K1_SMEM>>>(x, bq);

    cudaFuncSetAttribute(attn_only, cudaFuncAttributeMaxDynamicSharedMemorySize, K2_SMEM);
    attn_only<<<B_TOT / 2, 256, K2_SMEM>>>(mask);

    cudaFuncSetAttribute(proj_gemm, cudaFuncAttributeMaxDynamicSharedMemorySize, K3_SMEM);
    proj_gemm<<<QKV_ROWS / 128, 256, K3_SMEM>>>(bp, out);
}

// round 17
// speedup vs baseline: 1.4028x; 1.0049x over previous
#include <cstdint>
#include <stdint.h>
#include <cuda_runtime.h>
#include <cuda_fp16.h>

#define B_TOT   8192
#define NTOK    49
#define CDIM    192
#define NH      6
#define HDIM    32
#define SCALE_F 0.17677669529663687f   // 1/sqrt(32)
#define SCL2    0.25500526690087863f   // SCALE_F * log2(e)
#define QKV_ROWS (B_TOT * NTOK)        // 401408

// fp16 copies of the weights (converted by conv_w each call; deterministic)
__device__ __align__(16) __half g_wqkv[CDIM * 3 * CDIM];   // [192][576] row-major
__device__ __align__(16) __half g_wproj[CDIM * CDIM];      // [192][192] row-major
// fp16 qkv scratch, HEAD-MAJOR: [sec(3)][head(6)][b*49+n][32]
__device__ __align__(16) __half g_qkv[QKV_ROWS * 3 * CDIM];
// fp16 attention-output scratch: [B_*N][192] row-major
__device__ __align__(16) __half g_o[QKV_ROWS * CDIM];

__global__ void conv_w(const float* __restrict__ wq, const float* __restrict__ wp) {
    int i = blockIdx.x * 256 + threadIdx.x;
    if (i < CDIM * 3 * CDIM) g_wqkv[i]  = __float2half_rn(wq[i]);
    if (i < CDIM * CDIM)     g_wproj[i] = __float2half_rn(wp[i]);
}

// ---------------------------------------------------------------------------
// raw-PTX helpers
// ---------------------------------------------------------------------------
__device__ __forceinline__ unsigned smaddr(const void* p) {
    return (unsigned)__cvta_generic_to_shared(p);
}
__device__ __forceinline__ void ldsm4(unsigned& r0, unsigned& r1, unsigned& r2, unsigned& r3,
                                      unsigned a) {
    asm volatile("ldmatrix.sync.aligned.m8n8.x4.shared.b16 {%0,%1,%2,%3}, [%4];"
                 : "=r"(r0), "=r"(r1), "=r"(r2), "=r"(r3) : "r"(a));
}
__device__ __forceinline__ void ldsm4t(unsigned& r0, unsigned& r1, unsigned& r2, unsigned& r3,
                                       unsigned a) {
    asm volatile("ldmatrix.sync.aligned.m8n8.x4.trans.shared.b16 {%0,%1,%2,%3}, [%4];"
                 : "=r"(r0), "=r"(r1), "=r"(r2), "=r"(r3) : "r"(a));
}
__device__ __forceinline__ void mma16816(float* c,
                                         unsigned a0, unsigned a1, unsigned a2, unsigned a3,
                                         unsigned b0, unsigned b1) {
    asm volatile(
        "mma.sync.aligned.m16n8k16.row.col.f32.f16.f16.f32 "
        "{%0,%1,%2,%3},{%4,%5,%6,%7},{%8,%9},{%0,%1,%2,%3};"
        : "+f"(c[0]), "+f"(c[1]), "+f"(c[2]), "+f"(c[3])
        : "r"(a0), "r"(a1), "r"(a2), "r"(a3), "r"(b0), "r"(b1));
}
__device__ __forceinline__ unsigned pack_h2(float a, float b) {
    __half2 h = __floats2half2_rn(a, b);
    return *(unsigned*)&h;
}
__device__ __forceinline__ float ex2f(float x) {
    float r;
    asm("ex2.approx.f32 %0, %1;" : "=f"(r) : "f"(x));
    return r;
}
__device__ __forceinline__ void cp_async16(unsigned dst, const void* src) {
    asm volatile("cp.async.cg.shared.global [%0], [%1], 16;" :: "r"(dst), "l"(src));
}
__device__ __forceinline__ void cp_commit() {
    asm volatile("cp.async.commit_group;");
}
__device__ __forceinline__ void cp_wait0() {
    asm volatile("cp.async.wait_group 0;");
}

// ============================================================================
// Kernel 1: QKV projection GEMM, raw mma, double-buffered cp.async staging.
// Epilogue writes HEAD-MAJOR g_qkv: [sec][head][row][32]. (unchanged)
// ============================================================================
#define K1_SMEM 79872

__global__ void __launch_bounds__(256, 2)
qkv_gemm(const float* __restrict__ x, const float* __restrict__ bqkv)
{
    extern __shared__ __align__(128) char smem[];

    const int tid  = threadIdx.x;
    const int w    = tid >> 5;
    const int lane = tid & 31;
    const int rbase = blockIdx.x * 128 + w * 16;
    const int c0 = 2 * (lane & 3);

    {
        __half* wb = (__half*)smem;
        for (int i = tid; i < 2304; i += 256) {      // 192 rows * 12 int4
            int row = i / 12, v8 = i % 12;
            cp_async16(smaddr(wb + row * 104 + v8 * 8),
                       g_wqkv + row * 576 + v8 * 8);
        }
        cp_commit();
    }

    unsigned A[12][4];
    {
        const int r0 = rbase + (lane >> 2);
        const float* xr0 = x + (size_t)r0 * CDIM;
        const float* xr8 = xr0 + 8 * CDIM;
        #pragma unroll
        for (int kt = 0; kt < 12; kt++) {
            int c = kt * 16 + c0;
            float2 v;
            v = *(const float2*)(xr0 + c);     A[kt][0] = pack_h2(v.x, v.y);
            v = *(const float2*)(xr8 + c);     A[kt][1] = pack_h2(v.x, v.y);
            v = *(const float2*)(xr0 + c + 8); A[kt][2] = pack_h2(v.x, v.y);
            v = *(const float2*)(xr8 + c + 8); A[kt][3] = pack_h2(v.x, v.y);
        }
    }

    cp_wait0();
    __syncthreads();

    const int orow = rbase + (lane >> 2);

    for (int nc = 0; nc < 6; nc++) {
        __half* wsc = (__half*)(smem + (nc & 1) * 39936);

        if (nc < 5) {
            __half* wb = (__half*)(smem + ((nc + 1) & 1) * 39936);
            for (int i = tid; i < 2304; i += 256) {
                int row = i / 12, v8 = i % 12;
                cp_async16(smaddr(wb + row * 104 + v8 * 8),
                           g_wqkv + row * 576 + (nc + 1) * 96 + v8 * 8);
            }
            cp_commit();
        }

        float C[12][4];
        #pragma unroll
        for (int n = 0; n < 12; n++)
            #pragma unroll
            for (int e = 0; e < 4; e++) C[n][e] = 0.0f;

        #pragma unroll
        for (int kt = 0; kt < 12; kt++) {
            int rB = kt * 16 + (lane & 7) + ((lane >> 3) & 1) * 8;
            #pragma unroll
            for (int np = 0; np < 6; np++) {
                unsigned b0, b1, b2, b3;
                int cB = np * 16 + (lane >> 4) * 8;
                ldsm4t(b0, b1, b2, b3, smaddr(wsc + rB * 104 + cB));
                mma16816(C[2 * np],     A[kt][0], A[kt][1], A[kt][2], A[kt][3], b0, b1);
                mma16816(C[2 * np + 1], A[kt][0], A[kt][1], A[kt][2], A[kt][3], b2, b3);
            }
        }

        // ---- epilogue: +bias, fp16, head-major global store ----
        {
            const int sec   = nc >> 1;
            const int headb = (nc & 1) * 3;
            #pragma unroll
            for (int n = 0; n < 12; n++) {
                int head = headb + (n >> 2);
                int hd   = (n & 3) * 8 + c0;
                float2 bb = *(const float2*)(bqkv + nc * 96 + n * 8 + c0);
                __half* h0 = g_qkv +
                    ((size_t)(sec * 6 + head) * QKV_ROWS + orow) * 32 + hd;
                __half* h8 = h0 + (size_t)8 * 32;
                *(__half2*)h0 = __floats2half2_rn(C[n][0] + bb.x, C[n][1] + bb.y);
                *(__half2*)h8 = __floats2half2_rn(C[n][2] + bb.x, C[n][3] + bb.y);
            }
        }

        if (nc < 5) {
            cp_wait0();
            __syncthreads();
        }
    }
}

// ============================================================================
// Kernel 2: attention ONLY, FOUR batch items per CTA (grid 2048, 12 phases).
// Head-pair double buffering + contiguous cp.async. Softmax in log2 domain
// (SCALE*log2e folded into masking; raw ex2.approx). QK skips the always-
// padding n-tile (cols 56-63). smem: 2 bufs x 6 mats x 64 x 40 halves
// = 61440 B | mbs u32[8] @61440 -> 61472; 3 CTAs/SM.
// ============================================================================
#define MATS  2560                     // halves per matrix buffer (64 x 40)
#define PAIRB (6 * MATS)               // halves per pair buffer
#define K2_SMEM 61472

__global__ void __launch_bounds__(256, 3)
attn_only(const int* __restrict__ mask)
{
    extern __shared__ __align__(128) char smem[];
    __half*   qbufs = (__half*)(smem);               // 2 x PAIRB halves
    unsigned* mbs   = (unsigned*)(smem + 61440);     // 4 batches x 2 words

    const int b0   = blockIdx.x * 4;
    const int tid  = threadIdx.x;
    const int w    = tid >> 5;
    const int lane = tid & 31;
    const int q2   = 2 * (lane & 3);

    // ---- mask ballots for all four batches (warp w covers batch w>>1) ----
    {
        int bb  = tid >> 6;                          // 0..3
        int tok = tid & 63;
        int valid = (tok < NTOK) ? (mask[(b0 + bb) * NTOK + tok] != 0) : 0;
        unsigned bal = __ballot_sync(0xffffffffu, valid);
        if (lane == 0) mbs[w] = bal;
    }
    // ---- zero pad rows 49..63 of every matrix, both buffers ----
    for (int i = tid; i < 2 * 6 * 15 * 5; i += 256) {   // 900 int4
        int buf = i / 450, j = i % 450;
        int mat = j / 75, k = j % 75;
        int r = 49 + k / 5, v4 = k % 5;
        *(int4*)(qbufs + buf * PAIRB + mat * MATS + r * 40 + v4 * 8) =
            make_int4(0, 0, 0, 0);
    }
    // ---- stage phase 0 (batch b0, pair 0) into buf 0 ----
    for (int i = tid; i < 6 * NTOK * 4; i += 256) {     // 1176 int4
        int blk = i / (NTOK * 4), j = i % (NTOK * 4);
        int row = j / 4, v4 = j % 4;
        int hx = blk / 3, sec = blk % 3;
        cp_async16(smaddr(qbufs + (hx * 3 + sec) * MATS + row * 40 + v4 * 8),
                   g_qkv + ((size_t)(sec * 6 + hx) * QKV_ROWS + (size_t)b0 * NTOK + row) * 32 + v4 * 8);
    }
    cp_commit();

    const int hh = w >> 2;                 // head within pair
    const int m  = w & 3;                  // m-tile (16 q rows)

    for (int ph = 0; ph < 12; ph++) {
        cp_wait0();
        __syncthreads();   // buffer ph ready; compute ph-1 done (WAR for ph+1's buffer)

        const int bsel = ph / 3;           // which batch this phase computes
        const int hp   = ph - bsel * 3;    // head pair within batch
        const unsigned mb0 = mbs[2 * bsel], mb1 = mbs[2 * bsel + 1];

        // ---- prefetch phase ph+1 into the other buffer ----
        if (ph < 11) {
            const int nbsel = (ph + 1) / 3;
            const int nhp   = (ph + 1) - nbsel * 3;
            const size_t nb = (size_t)(b0 + nbsel) * NTOK;
            __half* wb = qbufs + ((ph + 1) & 1) * PAIRB;
            for (int i = tid; i < 6 * NTOK * 4; i += 256) {
                int blk = i / (NTOK * 4), j = i % (NTOK * 4);
                int row = j / 4, v4 = j % 4;
                int hx = blk / 3, sec = blk % 3;
                int h = nhp * 2 + hx;
                cp_async16(smaddr(wb + (hx * 3 + sec) * MATS + row * 40 + v4 * 8),
                           g_qkv + ((size_t)(sec * 6 + h) * QKV_ROWS + nb + row) * 32 + v4 * 8);
            }
            cp_commit();
        }

        __half* qsq = qbufs + (ph & 1) * PAIRB + (hh * 3 + 0) * MATS;
        __half* qsk = qbufs + (ph & 1) * PAIRB + (hh * 3 + 1) * MATS;
        __half* qsv = qbufs + (ph & 1) * PAIRB + (hh * 3 + 2) * MATS;

        // ---- GEMM2 in registers: S[16][64] = Q_tile @ K^T ----
        // cols 56-63 are ALWAYS padding (NTOK=49): skip their mma, seed -1e30.
        float s[32];
        #pragma unroll
        for (int i = 0; i < 28; i++) s[i] = 0.0f;
        #pragma unroll
        for (int i = 28; i < 32; i++) s[i] = -1e30f;

        #pragma unroll
        for (int kt = 0; kt < 2; kt++) {
            unsigned a0, a1, a2, a3;
            {
                int r = m * 16 + (lane & 7) + ((lane >> 3) & 1) * 8;
                int c = kt * 16 + (lane >> 4) * 8;
                ldsm4(a0, a1, a2, a3, smaddr(qsq + r * 40 + c));
            }
            #pragma unroll
            for (int ng = 0; ng < 4; ng++) {
                unsigned b0r, b1r, b2r, b3r;
                int r = ng * 16 + (lane & 7) + (lane >> 4) * 8;
                int c = kt * 16 + ((lane >> 3) & 1) * 8;
                ldsm4(b0r, b1r, b2r, b3r, smaddr(qsk + r * 40 + c));
                mma16816(s + (2 * ng) * 4, a0, a1, a2, a3, b0r, b1r);
                if (ng < 3)
                    mma16816(s + (2 * ng + 1) * 4, a0, a1, a2, a3, b2r, b3r);
            }
        }

        // ---- masked softmax in log2 domain (scale*log2e folded in) ----
        float mxA = -1e30f, mxB = -1e30f;
        #pragma unroll
        for (int t = 0; t < 7; t++) {
            int c0 = 8 * t + q2;
            unsigned vm = (c0 < 32) ? (mb0 >> c0) : (mb1 >> (c0 - 32));
            s[4 * t + 0] = (vm & 1) ? s[4 * t + 0] * SCL2 : -1e30f;
            s[4 * t + 1] = (vm & 2) ? s[4 * t + 1] * SCL2 : -1e30f;
            s[4 * t + 2] = (vm & 1) ? s[4 * t + 2] * SCL2 : -1e30f;
            s[4 * t + 3] = (vm & 2) ? s[4 * t + 3] * SCL2 : -1e30f;
            mxA = fmaxf(mxA, fmaxf(s[4 * t + 0], s[4 * t + 1]));
            mxB = fmaxf(mxB, fmaxf(s[4 * t + 2], s[4 * t + 3]));
        }
        mxA = fmaxf(mxA, __shfl_xor_sync(0xffffffffu, mxA, 1));
        mxA = fmaxf(mxA, __shfl_xor_sync(0xffffffffu, mxA, 2));
        mxB = fmaxf(mxB, __shfl_xor_sync(0xffffffffu, mxB, 1));
        mxB = fmaxf(mxB, __shfl_xor_sync(0xffffffffu, mxB, 2));

        float smA = 0.0f, smB = 0.0f;
        #pragma unroll
        for (int t = 0; t < 8; t++) {
            s[4 * t + 0] = ex2f(s[4 * t + 0] - mxA);
            s[4 * t + 1] = ex2f(s[4 * t + 1] - mxA);
            s[4 * t + 2] = ex2f(s[4 * t + 2] - mxB);
            s[4 * t + 3] = ex2f(s[4 * t + 3] - mxB);
            smA += s[4 * t + 0] + s[4 * t + 1];
            smB += s[4 * t + 2] + s[4 * t + 3];
        }
        smA += __shfl_xor_sync(0xffffffffu, smA, 1);
        smA += __shfl_xor_sync(0xffffffffu, smA, 2);
        smB += __shfl_xor_sync(0xffffffffu, smB, 1);
        smB += __shfl_xor_sync(0xffffffffu, smB, 2);
        const float invA = 1.0f / smA, invB = 1.0f / smB;

        // ---- P accumulator -> A-fragments ----
        unsigned pa[16];
        #pragma unroll
        for (int kc = 0; kc < 4; kc++) {
            float* t0 = s + (2 * kc) * 4;
            float* t1 = s + (2 * kc + 1) * 4;
            pa[4 * kc + 0] = pack_h2(t0[0] * invA, t0[1] * invA);
            pa[4 * kc + 1] = pack_h2(t0[2] * invB, t0[3] * invB);
            pa[4 * kc + 2] = pack_h2(t1[0] * invA, t1[1] * invA);
            pa[4 * kc + 3] = pack_h2(t1[2] * invB, t1[3] * invB);
        }

        // ---- GEMM3: O[16][32] = P @ V ----
        float o[16];
        #pragma unroll
        for (int i = 0; i < 16; i++) o[i] = 0.0f;
        #pragma unroll
        for (int kc = 0; kc < 4; kc++) {
            #pragma unroll
            for (int nh = 0; nh < 2; nh++) {
                unsigned b0r, b1r, b2r, b3r;
                int r = kc * 16 + (lane & 7) + ((lane >> 3) & 1) * 8;
                int c = nh * 16 + (lane >> 4) * 8;
                ldsm4t(b0r, b1r, b2r, b3r, smaddr(qsv + r * 40 + c));
                mma16816(o + (2 * nh) * 4,
                         pa[4 * kc + 0], pa[4 * kc + 1], pa[4 * kc + 2], pa[4 * kc + 3],
                         b0r, b1r);
                mma16816(o + (2 * nh + 1) * 4,
                         pa[4 * kc + 0], pa[4 * kc + 1], pa[4 * kc + 2], pa[4 * kc + 3],
                         b2r, b3r);
            }
        }

        // ---- store O tile directly to g_o scratch (fp16) ----
        {
            int h  = hp * 2 + hh;
            int rA = m * 16 + (lane >> 2);
            __half* r0p = g_o + ((size_t)(b0 + bsel) * NTOK + rA) * CDIM + h * HDIM;
            __half* r8p = r0p + (size_t)8 * CDIM;
            #pragma unroll
            for (int t = 0; t < 4; t++) {
                int col = 8 * t + q2;
                if (rA < NTOK)
                    *(__half2*)(r0p + col) = __floats2half2_rn(o[4 * t + 0], o[4 * t + 1]);
                if (rA + 8 < NTOK)
                    *(__half2*)(r8p + col) = __floats2half2_rn(o[4 * t + 2], o[4 * t + 3]);
            }
        }
    }
}

// ============================================================================
// Kernel 3: output projection GEMM, 256 rows/CTA (grid 1568, 4 sub-blocks):
// weight staging amortized 2x vs round 15. Otherwise identical structure.
// ============================================================================
#define K3_SMEM 105472

__global__ void __launch_bounds__(256, 2)
proj_gemm(const float* __restrict__ bproj, float* __restrict__ out)
{
    extern __shared__ __align__(128) char smem[];
    __half* wsc  = (__half*)smem;                   // 2 chunks, stride 19968 halves
    __half* abuf = (__half*)(smem + 79872);         // [64][200] halves

    const int tid  = threadIdx.x;
    const int w    = tid >> 5;
    const int lane = tid & 31;
    const int rbase0 = blockIdx.x * 256;
    const int c0 = 2 * (lane & 3);
    const int mt = w & 3;                            // m-tile within 64-row sub-block
    const int ch = w >> 2;                           // 96-col half

    // ---- stage both weight chunks + A sub-block 0 (one cp.async group) ----
    for (int i = tid; i < 4608; i += 256) {          // 2 ch x 192 rows x 12 int4
        int cc = i / 2304, j = i % 2304;
        int row = j / 12, v8 = j % 12;
        cp_async16(smaddr(wsc + cc * 19968 + row * 104 + v8 * 8),
                   g_wproj + row * 192 + cc * 96 + v8 * 8);
    }
    for (int i = tid; i < 1536; i += 256) {          // 64 rows x 24 int4
        int row = i / 24, v8 = i % 24;
        cp_async16(smaddr(abuf + row * 200 + v8 * 8),
                   g_o + (size_t)(rbase0 + row) * CDIM + v8 * 8);
    }
    cp_commit();
    cp_wait0();
    __syncthreads();

    __half* wc = wsc + ch * 19968;

    #pragma unroll
    for (int blk = 0; blk < 4; blk++) {
        // ---- A-fragments from abuf via ldsm4 (row stride 400B) ----
        unsigned A[12][4];
        {
            int r = mt * 16 + (lane & 7) + ((lane >> 3) & 1) * 8;
            #pragma unroll
            for (int kt = 0; kt < 12; kt++) {
                int c = kt * 16 + (lane >> 4) * 8;
                ldsm4(A[kt][0], A[kt][1], A[kt][2], A[kt][3],
                      smaddr(abuf + r * 200 + c));
            }
        }
        __syncthreads();   // all warps done reading abuf

        // ---- overlap: stage sub-block blk+1 while computing blk ----
        if (blk < 3) {
            for (int i = tid; i < 1536; i += 256) {
                int row = i / 24, v8 = i % 24;
                cp_async16(smaddr(abuf + row * 200 + v8 * 8),
                           g_o + (size_t)(rbase0 + (blk + 1) * 64 + row) * CDIM + v8 * 8);
            }
            cp_commit();
        }

        float C[12][4];
        #pragma unroll
        for (int n = 0; n < 12; n++)
            #pragma unroll
            for (int e = 0; e < 4; e++) C[n][e] = 0.0f;

        #pragma unroll
        for (int kt = 0; kt < 12; kt++) {
            int rB = kt * 16 + (lane & 7) + ((lane >> 3) & 1) * 8;
            #pragma unroll
            for (int np = 0; np < 6; np++) {
                unsigned b0, b1, b2, b3;
                int cB = np * 16 + (lane >> 4) * 8;
                ldsm4t(b0, b1, b2, b3, smaddr(wc + rB * 104 + cB));
                mma16816(C[2 * np],     A[kt][0], A[kt][1], A[kt][2], A[kt][3], b0, b1);
                mma16816(C[2 * np + 1], A[kt][0], A[kt][1], A[kt][2], A[kt][3], b2, b3);
            }
        }

        // ---- epilogue: +bias, float2 direct stores ----
        {
            int orow = rbase0 + blk * 64 + mt * 16 + (lane >> 2);
            float* g0 = out + (size_t)orow * CDIM + ch * 96;
            float* g8 = g0 + (size_t)8 * CDIM;
            #pragma unroll
            for (int n = 0; n < 12; n++) {
                int col = 8 * n + c0;
                float2 bb = *(const float2*)(bproj + ch * 96 + col);
                *(float2*)(g0 + col) = make_float2(C[n][0] + bb.x, C[n][1] + bb.y);
                *(float2*)(g8 + col) = make_float2(C[n][2] + bb.x, C[n][3] + bb.y);
            }
        }

        if (blk < 3) {
            cp_wait0();
            __syncthreads();   // abuf now holds sub-block blk+1
        }
    }
}

extern "C" void kernel_launch(void* const* d_in, const int* in_sizes, int n_in,
                              void* d_out, int out_size)
{
    (void)in_sizes; (void)n_in; (void)out_size;
    const float* x    = (const float*)d_in[0];
    const int*   mask = (const int*)  d_in[1];
    const float* wq   = (const float*)d_in[2];
    const float* bq   = (const float*)d_in[3];
    const float* wpj  = (const float*)d_in[4];
    const float* bp   = (const float*)d_in[5];
    float* out = (float*)d_out;

    conv_w<<<(CDIM * 3 * CDIM + 255) / 256, 256>>>(wq, wpj);

    cudaFuncSetAttribute(qkv_gemm, cudaFuncAttributeMaxDynamicSharedMemorySize, K1_SMEM);
    qkv_gemm<<<QKV_ROWS / 128, 256, K1_SMEM>>>(x, bq);

    cudaFuncSetAttribute(attn_only, cudaFuncAttributeMaxDynamicSharedMemorySize, K2_SMEM);
    attn_only<<<B_TOT / 4, 256, K2_SMEM>>>(mask);

    cudaFuncSetAttribute(proj_gemm, cudaFuncAttributeMaxDynamicSharedMemorySize, K3_SMEM);
    proj_gemm<<<QKV_ROWS / 256, 256, K3_SMEM>>>(bp, out);
}